// round 5
// baseline (speedup 1.0000x reference)
#include <cuda_runtime.h>
#include <cuda_bf16.h>
#include <math.h>

#define NTOK 294      // 6*7*7 tokens per window
#define NWIN 256      // 16*16 windows
#define NHEAD 8
#define DH 32
#define DIM 256
#define QSCALE 0.17677669529663687f  // 32^-0.5

typedef unsigned long long u64;

// packed fp32x2 FMA (Blackwell): d = a*b + c elementwise on 2 floats
#define FMA2(d, a, b, c) \
    asm("fma.rn.f32x2 %0, %1, %2, %3;" : "=l"(d) : "l"(a), "l"(b), "l"(c))

__device__ __forceinline__ u64 pkdup(float v) {
    u64 r; asm("mov.b64 %0, {%1, %1};" : "=l"(r) : "f"(v)); return r;
}
__device__ __forceinline__ float foldadd(u64 v) {
    float lo, hi; asm("mov.b64 {%0, %1}, %2;" : "=f"(lo), "=f"(hi) : "l"(v));
    return lo + hi;
}
__device__ __forceinline__ void unpk(u64 v, float& lo, float& hi) {
    asm("mov.b64 {%0, %1}, %2;" : "=f"(lo), "=f"(hi) : "l"(v));
}

// -------- scratch (device globals; no allocations allowed) --------
__device__ float g_Q[(size_t)NWIN*NHEAD*NTOK*DH];
__device__ float g_K[(size_t)NWIN*NHEAD*NTOK*DH];
__device__ float g_V[(size_t)NWIN*NHEAD*NTOK*DH];
__device__ float g_O[(size_t)NWIN*NHEAD*NTOK*DH];
__device__ float g_bias[(size_t)NHEAD*NTOK*NTOK];

// ======================================================================
// 1) Precompute relative position bias matrix bias[h][i][j]
// ======================================================================
__global__ void bias_kernel(const float* __restrict__ table) {
    int i = blockIdx.x;
    int j = threadIdx.x;
    int ai = i / 49, ri = i % 49, yi = ri / 7, xi = ri % 7;
    int aj = j / 49, rj = j % 49, yj = rj / 7, xj = rj % 7;
    int idx = (ai - aj + 5) * 169 + (yi - yj + 6) * 13 + (xi - xj + 6);
#pragma unroll
    for (int h = 0; h < NHEAD; h++)
        g_bias[((size_t)h * NTOK + i) * NTOK + j] = table[idx * NHEAD + h];
}

// ======================================================================
// 2) QKV projection (tiled SGEMM, f32x2 inner product, fused scatter)
// ======================================================================
__global__ __launch_bounds__(256) void qkv_gemm(
    const float* __restrict__ x, const float* __restrict__ w) {
    __shared__ float As[16][132];
    __shared__ float Bs[16][132];
    int tid = threadIdx.x;
    int bm = blockIdx.x, bn = blockIdx.y;

    int lrow = tid >> 2;            // 0..63
    int kq   = (tid & 3) << 2;      // 0,4,8,12

    const float *ap0, *ap1;
    {
        int m0 = bm * 128 + lrow;
        int Bw = m0 / 294, t = m0 % 294, l = t / 49, r = t % 49;
        ap0 = x + ((size_t)((l * 256 + Bw) * 49 + r)) * 256;
        int m1 = m0 + 64;
        Bw = m1 / 294; t = m1 % 294; l = t / 49; r = t % 49;
        ap1 = x + ((size_t)((l * 256 + Bw) * 49 + r)) * 256;
    }
    const float* bp0 = w + (size_t)(bn * 128 + lrow) * 256;
    const float* bp1 = bp0 + (size_t)64 * 256;

    int tx = tid & 15, ty = tid >> 4;
    u64 c2[8][4];
#pragma unroll
    for (int i = 0; i < 8; i++)
#pragma unroll
        for (int j = 0; j < 4; j++) c2[i][j] = 0ULL;

    for (int k0 = 0; k0 < 256; k0 += 16) {
        float4 a0 = *(const float4*)(ap0 + k0 + kq);
        float4 a1 = *(const float4*)(ap1 + k0 + kq);
        float4 b0 = *(const float4*)(bp0 + k0 + kq);
        float4 b1 = *(const float4*)(bp1 + k0 + kq);
        __syncthreads();
        As[kq + 0][lrow] = a0.x; As[kq + 1][lrow] = a0.y;
        As[kq + 2][lrow] = a0.z; As[kq + 3][lrow] = a0.w;
        As[kq + 0][lrow + 64] = a1.x; As[kq + 1][lrow + 64] = a1.y;
        As[kq + 2][lrow + 64] = a1.z; As[kq + 3][lrow + 64] = a1.w;
        Bs[kq + 0][lrow] = b0.x; Bs[kq + 1][lrow] = b0.y;
        Bs[kq + 2][lrow] = b0.z; Bs[kq + 3][lrow] = b0.w;
        Bs[kq + 0][lrow + 64] = b1.x; Bs[kq + 1][lrow + 64] = b1.y;
        Bs[kq + 2][lrow + 64] = b1.z; Bs[kq + 3][lrow + 64] = b1.w;
        __syncthreads();
#pragma unroll
        for (int kk = 0; kk < 16; kk++) {
            u64 a2[8], bv2[4];
#pragma unroll
            for (int i = 0; i < 8; i++) a2[i] = pkdup(As[kk][ty * 8 + i]);
#pragma unroll
            for (int j = 0; j < 4; j++)
                bv2[j] = *(const u64*)(&Bs[kk][tx * 8 + 2 * j]);
#pragma unroll
            for (int i = 0; i < 8; i++)
#pragma unroll
                for (int j = 0; j < 4; j++)
                    FMA2(c2[i][j], a2[i], bv2[j], c2[i][j]);
        }
    }

#pragma unroll
    for (int ii = 0; ii < 8; ii++) {
        int m = bm * 128 + ty * 8 + ii;
        int Bw = m / 294, t = m % 294;
#pragma unroll
        for (int j2 = 0; j2 < 4; j2++) {
            float vlo, vhi;
            unpk(c2[ii][j2], vlo, vhi);
#pragma unroll
            for (int half = 0; half < 2; half++) {
                int n = bn * 128 + tx * 8 + 2 * j2 + half;
                int part = n >> 8;
                int rem = n & 255;
                int head = rem >> 5, dh = rem & 31;
                size_t o = (((size_t)Bw * 8 + head) * NTOK + t) * DH + dh;
                float v = half ? vhi : vlo;
                if (part == 0)      g_Q[o] = v * QSCALE;
                else if (part == 1) g_K[o] = v;
                else                g_V[o] = v;
            }
        }
    }
}

// ======================================================================
// 3) Attention: 4 query rows/warp, f32x2 packed over the reduction axis
//    (d-pairs in QK, j-pairs in AV via transposed V). 2 blocks/SM.
// ======================================================================
#define KSTR 36
#define VTSTR 324   // transposed V row stride (conflict-free LDS.128)
__global__ __launch_bounds__(256, 2) void attn_kernel() {
    int bh = blockIdx.x;            // Bw*8 + h
    int h = bh & 7;
    extern __shared__ float sm[];
    float* Ks = sm;                       // 294*36   = 10584
    float* Vt = Ks + NTOK * KSTR;         // 32*324   = 10368 (V transposed)
    float* Ps = Vt + DH * VTSTR;          // 8*256    =  2048 (dbl-buf 4x32/warp)
    float* Qr = Ps + 8 * 256;             // 8*128    =  1024
    // total 24024 floats = 93.8 KB -> 2 blocks/SM

    const float* Kg = g_K + (size_t)bh * NTOK * DH;
    const float* Vg = g_V + (size_t)bh * NTOK * DH;
    const float* Qg = g_Q + (size_t)bh * NTOK * DH;
    const float* Bb = g_bias + (size_t)h * NTOK * NTOK;

    int tid = threadIdx.x;
    for (int idx = tid; idx < NTOK * DH; idx += 256) {
        int j = idx >> 5, d = idx & 31;
        Ks[j * KSTR + d] = Kg[idx];
    }
    // V transposed: Vt[d][j], zero-padded to j<320
    for (int idx = tid; idx < 320 * DH; idx += 256) {
        int d = idx & 31, j = idx >> 5;
        Vt[d * VTSTR + j] = (j < NTOK) ? Vg[j * DH + d] : 0.f;
    }
    __syncthreads();

    int w = tid >> 5, lane = tid & 31;
    float* Pw = Ps + w * 256;             // two 128-float buffers
    float* Qw = Qr + w * 4 * DH;

    for (int i0 = w * 4; i0 < NTOK; i0 += 32) {
        // stage 4 q rows into smem
#pragma unroll
        for (int r = 0; r < 4; r++) {
            int i = i0 + r; if (i >= NTOK) i = NTOK - 1;
            Qw[r * DH + lane] = Qg[i * DH + lane];
        }
        __syncwarp();

        float s[4][10];

        // QK^T in two 5-strip halves (keeps accumulator pressure low).
        // Packed over d: s2 halves hold (even-d, odd-d) partial sums.
#pragma unroll
        for (int half = 0; half < 2; half++) {
            const float* kp[5];
#pragma unroll
            for (int jj = 0; jj < 5; jj++) {
                int j = lane + (half * 5 + jj) * 32;
                kp[jj] = Ks + (j < NTOK ? j : NTOK - 1) * KSTR;
            }
            u64 s2[4][5];
#pragma unroll
            for (int r = 0; r < 4; r++) {
                int i = i0 + r; if (i >= NTOK) i = NTOK - 1;
                const float* bi = Bb + (size_t)i * NTOK;
#pragma unroll
                for (int jj = 0; jj < 5; jj++) {
                    int j = lane + (half * 5 + jj) * 32;
                    // lo half carries bias (or -inf mask), hi half 0
                    s2[r][jj] = (u64)__float_as_uint(j < NTOK ? bi[j] : -1e30f);
                }
            }
#pragma unroll
            for (int d4 = 0; d4 < 8; d4++) {
                ulonglong2 q0 = *(const ulonglong2*)(Qw + 0 * DH + d4 * 4);
                ulonglong2 q1 = *(const ulonglong2*)(Qw + 1 * DH + d4 * 4);
                ulonglong2 q2 = *(const ulonglong2*)(Qw + 2 * DH + d4 * 4);
                ulonglong2 q3 = *(const ulonglong2*)(Qw + 3 * DH + d4 * 4);
#pragma unroll
                for (int jj = 0; jj < 5; jj++) {
                    ulonglong2 kv = *(const ulonglong2*)(kp[jj] + d4 * 4);
                    FMA2(s2[0][jj], q0.x, kv.x, s2[0][jj]);
                    FMA2(s2[0][jj], q0.y, kv.y, s2[0][jj]);
                    FMA2(s2[1][jj], q1.x, kv.x, s2[1][jj]);
                    FMA2(s2[1][jj], q1.y, kv.y, s2[1][jj]);
                    FMA2(s2[2][jj], q2.x, kv.x, s2[2][jj]);
                    FMA2(s2[2][jj], q2.y, kv.y, s2[2][jj]);
                    FMA2(s2[3][jj], q3.x, kv.x, s2[3][jj]);
                    FMA2(s2[3][jj], q3.y, kv.y, s2[3][jj]);
                }
            }
#pragma unroll
            for (int r = 0; r < 4; r++)
#pragma unroll
                for (int jj = 0; jj < 5; jj++)
                    s[r][half * 5 + jj] = foldadd(s2[r][jj]);
        }

        // softmax per row (OOB j -> exp(-1e30-mx) = 0)
        float inv[4];
#pragma unroll
        for (int r = 0; r < 4; r++) {
            float mx = -1e30f;
#pragma unroll
            for (int jj = 0; jj < 10; jj++) mx = fmaxf(mx, s[r][jj]);
#pragma unroll
            for (int o = 16; o > 0; o >>= 1)
                mx = fmaxf(mx, __shfl_xor_sync(0xffffffffu, mx, o));
            float sum = 0.f;
#pragma unroll
            for (int jj = 0; jj < 10; jj++) {
                float e = __expf(s[r][jj] - mx);
                s[r][jj] = e;
                sum += e;
            }
#pragma unroll
            for (int o = 16; o > 0; o >>= 1)
                sum += __shfl_xor_sync(0xffffffffu, sum, o);
            inv[r] = 1.f / sum;
        }

        // strip-wise A*V, packed over j-pairs via transposed V
        u64 acc2[4] = {0ULL, 0ULL, 0ULL, 0ULL};
        const float* vrow = Vt + lane * VTSTR;
#pragma unroll
        for (int jj = 0; jj < 10; jj++) {
            float* Pb = Pw + (jj & 1) * 128;
            Pb[0 * 32 + lane] = s[0][jj];
            Pb[1 * 32 + lane] = s[1][jj];
            Pb[2 * 32 + lane] = s[2][jj];
            Pb[3 * 32 + lane] = s[3][jj];
            __syncwarp();
            const float* vs = vrow + jj * 32;
#pragma unroll
            for (int m4 = 0; m4 < 8; m4++) {
                ulonglong2 vv = *(const ulonglong2*)(vs + m4 * 4);
                ulonglong2 p0 = *(const ulonglong2*)(Pb + 0 * 32 + m4 * 4);
                ulonglong2 p1 = *(const ulonglong2*)(Pb + 1 * 32 + m4 * 4);
                ulonglong2 p2 = *(const ulonglong2*)(Pb + 2 * 32 + m4 * 4);
                ulonglong2 p3 = *(const ulonglong2*)(Pb + 3 * 32 + m4 * 4);
                FMA2(acc2[0], p0.x, vv.x, acc2[0]);
                FMA2(acc2[0], p0.y, vv.y, acc2[0]);
                FMA2(acc2[1], p1.x, vv.x, acc2[1]);
                FMA2(acc2[1], p1.y, vv.y, acc2[1]);
                FMA2(acc2[2], p2.x, vv.x, acc2[2]);
                FMA2(acc2[2], p2.y, vv.y, acc2[2]);
                FMA2(acc2[3], p3.x, vv.x, acc2[3]);
                FMA2(acc2[3], p3.y, vv.y, acc2[3]);
            }
            __syncwarp();
        }

#pragma unroll
        for (int r = 0; r < 4; r++) {
            int i = i0 + r;
            if (i < NTOK)
                g_O[((size_t)bh * NTOK + i) * DH + lane] = foldadd(acc2[r]) * inv[r];
        }
        __syncwarp();
    }
}

// ======================================================================
// 4) Output projection (tiled SGEMM, f32x2, fused gather + scatter)
// ======================================================================
__global__ __launch_bounds__(256) void out_gemm(
    const float* __restrict__ w, float* __restrict__ out) {
    __shared__ float As[16][132];
    __shared__ float Bs[16][132];
    int tid = threadIdx.x;
    int bm = blockIdx.x, bn = blockIdx.y;

    int lrow = tid >> 2;
    int kq   = (tid & 3) << 2;

    int m0 = bm * 128 + lrow;
    int Bw0 = m0 / 294, t0 = m0 % 294;
    int m1 = m0 + 64;
    int Bw1 = m1 / 294, t1 = m1 % 294;

    const float* bp0 = w + (size_t)(bn * 128 + lrow) * 256;
    const float* bp1 = bp0 + (size_t)64 * 256;

    int tx = tid & 15, ty = tid >> 4;
    u64 c2[8][4];
#pragma unroll
    for (int i = 0; i < 8; i++)
#pragma unroll
        for (int j = 0; j < 4; j++) c2[i][j] = 0ULL;

    for (int k0 = 0; k0 < 256; k0 += 16) {
        int kk0 = k0 + kq;
        int head = kk0 >> 5, dh = kk0 & 31;
        const float* ap0 = g_O + (((size_t)Bw0 * 8 + head) * NTOK + t0) * DH + dh;
        const float* ap1 = g_O + (((size_t)Bw1 * 8 + head) * NTOK + t1) * DH + dh;
        float4 a0 = *(const float4*)ap0;
        float4 a1 = *(const float4*)ap1;
        float4 b0 = *(const float4*)(bp0 + k0 + kq);
        float4 b1 = *(const float4*)(bp1 + k0 + kq);
        __syncthreads();
        As[kq + 0][lrow] = a0.x; As[kq + 1][lrow] = a0.y;
        As[kq + 2][lrow] = a0.z; As[kq + 3][lrow] = a0.w;
        As[kq + 0][lrow + 64] = a1.x; As[kq + 1][lrow + 64] = a1.y;
        As[kq + 2][lrow + 64] = a1.z; As[kq + 3][lrow + 64] = a1.w;
        Bs[kq + 0][lrow] = b0.x; Bs[kq + 1][lrow] = b0.y;
        Bs[kq + 2][lrow] = b0.z; Bs[kq + 3][lrow] = b0.w;
        Bs[kq + 0][lrow + 64] = b1.x; Bs[kq + 1][lrow + 64] = b1.y;
        Bs[kq + 2][lrow + 64] = b1.z; Bs[kq + 3][lrow + 64] = b1.w;
        __syncthreads();
#pragma unroll
        for (int kk = 0; kk < 16; kk++) {
            u64 a2[8], bv2[4];
#pragma unroll
            for (int i = 0; i < 8; i++) a2[i] = pkdup(As[kk][ty * 8 + i]);
#pragma unroll
            for (int j = 0; j < 4; j++)
                bv2[j] = *(const u64*)(&Bs[kk][tx * 8 + 2 * j]);
#pragma unroll
            for (int i = 0; i < 8; i++)
#pragma unroll
                for (int j = 0; j < 4; j++)
                    FMA2(c2[i][j], a2[i], bv2[j], c2[i][j]);
        }
    }

#pragma unroll
    for (int ii = 0; ii < 8; ii++) {
        int m = bm * 128 + ty * 8 + ii;
        int Bw = m / 294, t = m % 294, l = t / 49, r = t % 49;
        float* op = out + ((size_t)((l * 256 + Bw) * 49 + r)) * 256 + bn * 128 + tx * 8;
        float c[8];
#pragma unroll
        for (int j2 = 0; j2 < 4; j2++) unpk(c2[ii][j2], c[2 * j2], c[2 * j2 + 1]);
        *(float4*)(op)     = make_float4(c[0], c[1], c[2], c[3]);
        *(float4*)(op + 4) = make_float4(c[4], c[5], c[6], c[7]);
    }
}

// ======================================================================
extern "C" void kernel_launch(void* const* d_in, const int* in_sizes, int n_in,
                              void* d_out, int out_size) {
    const float* x          = (const float*)d_in[0];
    const float* w_qkv      = (const float*)d_in[1];
    const float* w_out      = (const float*)d_in[2];
    const float* bias_table = (const float*)d_in[3];
    float* out = (float*)d_out;

    bias_kernel<<<NTOK, NTOK>>>(bias_table);
    qkv_gemm<<<dim3(588, 6), 256>>>(x, w_qkv);

    int smem = (NTOK * KSTR + DH * VTSTR + 8 * 256 + 8 * 128) * (int)sizeof(float);
    cudaFuncSetAttribute(attn_kernel, cudaFuncAttributeMaxDynamicSharedMemorySize, smem);
    attn_kernel<<<NWIN * NHEAD, 256, smem>>>();

    out_gemm<<<dim3(588, 2), 256>>>(w_out, out);
}

// round 6
// speedup vs baseline: 1.0018x; 1.0018x over previous
#include <cuda_runtime.h>
#include <cuda_bf16.h>
#include <math.h>

#define NTOK 294      // 6*7*7 tokens per window
#define NWIN 256      // 16*16 windows
#define NHEAD 8
#define DH 32
#define DIM 256
#define QSCALE 0.17677669529663687f  // 32^-0.5

typedef unsigned long long u64;

// packed fp32x2 FMA (Blackwell): d = a*b + c elementwise on 2 floats
#define FMA2(d, a, b, c) \
    asm("fma.rn.f32x2 %0, %1, %2, %3;" : "=l"(d) : "l"(a), "l"(b), "l"(c))

__device__ __forceinline__ u64 pkdup(float v) {
    u64 r; asm("mov.b64 %0, {%1, %1};" : "=l"(r) : "f"(v)); return r;
}
__device__ __forceinline__ float foldadd(u64 v) {
    float lo, hi; asm("mov.b64 {%0, %1}, %2;" : "=f"(lo), "=f"(hi) : "l"(v));
    return lo + hi;
}
__device__ __forceinline__ void unpk(u64 v, float& lo, float& hi) {
    asm("mov.b64 {%0, %1}, %2;" : "=f"(lo), "=f"(hi) : "l"(v));
}

// -------- scratch (device globals; no allocations allowed) --------
__device__ float g_Q[(size_t)NWIN*NHEAD*NTOK*DH];
__device__ float g_K[(size_t)NWIN*NHEAD*NTOK*DH];
__device__ float g_V[(size_t)NWIN*NHEAD*NTOK*DH];
__device__ float g_O[(size_t)NWIN*NHEAD*NTOK*DH];
__device__ float g_bias[(size_t)NHEAD*NTOK*NTOK];

// ======================================================================
// 1) Precompute relative position bias matrix bias[h][i][j]
// ======================================================================
__global__ void bias_kernel(const float* __restrict__ table) {
    int i = blockIdx.x;
    int j = threadIdx.x;
    int ai = i / 49, ri = i % 49, yi = ri / 7, xi = ri % 7;
    int aj = j / 49, rj = j % 49, yj = rj / 7, xj = rj % 7;
    int idx = (ai - aj + 5) * 169 + (yi - yj + 6) * 13 + (xi - xj + 6);
#pragma unroll
    for (int h = 0; h < NHEAD; h++)
        g_bias[((size_t)h * NTOK + i) * NTOK + j] = table[idx * NHEAD + h];
}

// ======================================================================
// 2) QKV projection (tiled SGEMM, f32x2 inner product, fused scatter)
// ======================================================================
__global__ __launch_bounds__(256) void qkv_gemm(
    const float* __restrict__ x, const float* __restrict__ w) {
    __shared__ float As[16][132];
    __shared__ float Bs[16][132];
    int tid = threadIdx.x;
    int bm = blockIdx.x, bn = blockIdx.y;

    int lrow = tid >> 2;            // 0..63
    int kq   = (tid & 3) << 2;      // 0,4,8,12

    const float *ap0, *ap1;
    {
        int m0 = bm * 128 + lrow;
        int Bw = m0 / 294, t = m0 % 294, l = t / 49, r = t % 49;
        ap0 = x + ((size_t)((l * 256 + Bw) * 49 + r)) * 256;
        int m1 = m0 + 64;
        Bw = m1 / 294; t = m1 % 294; l = t / 49; r = t % 49;
        ap1 = x + ((size_t)((l * 256 + Bw) * 49 + r)) * 256;
    }
    const float* bp0 = w + (size_t)(bn * 128 + lrow) * 256;
    const float* bp1 = bp0 + (size_t)64 * 256;

    int tx = tid & 15, ty = tid >> 4;
    u64 c2[8][4];
#pragma unroll
    for (int i = 0; i < 8; i++)
#pragma unroll
        for (int j = 0; j < 4; j++) c2[i][j] = 0ULL;

    for (int k0 = 0; k0 < 256; k0 += 16) {
        float4 a0 = *(const float4*)(ap0 + k0 + kq);
        float4 a1 = *(const float4*)(ap1 + k0 + kq);
        float4 b0 = *(const float4*)(bp0 + k0 + kq);
        float4 b1 = *(const float4*)(bp1 + k0 + kq);
        __syncthreads();
        As[kq + 0][lrow] = a0.x; As[kq + 1][lrow] = a0.y;
        As[kq + 2][lrow] = a0.z; As[kq + 3][lrow] = a0.w;
        As[kq + 0][lrow + 64] = a1.x; As[kq + 1][lrow + 64] = a1.y;
        As[kq + 2][lrow + 64] = a1.z; As[kq + 3][lrow + 64] = a1.w;
        Bs[kq + 0][lrow] = b0.x; Bs[kq + 1][lrow] = b0.y;
        Bs[kq + 2][lrow] = b0.z; Bs[kq + 3][lrow] = b0.w;
        Bs[kq + 0][lrow + 64] = b1.x; Bs[kq + 1][lrow + 64] = b1.y;
        Bs[kq + 2][lrow + 64] = b1.z; Bs[kq + 3][lrow + 64] = b1.w;
        __syncthreads();
#pragma unroll
        for (int kk = 0; kk < 16; kk++) {
            u64 a2[8], bv2[4];
#pragma unroll
            for (int i = 0; i < 8; i++) a2[i] = pkdup(As[kk][ty * 8 + i]);
#pragma unroll
            for (int j = 0; j < 4; j++)
                bv2[j] = *(const u64*)(&Bs[kk][tx * 8 + 2 * j]);
#pragma unroll
            for (int i = 0; i < 8; i++)
#pragma unroll
                for (int j = 0; j < 4; j++)
                    FMA2(c2[i][j], a2[i], bv2[j], c2[i][j]);
        }
    }

#pragma unroll
    for (int ii = 0; ii < 8; ii++) {
        int m = bm * 128 + ty * 8 + ii;
        int Bw = m / 294, t = m % 294;
#pragma unroll
        for (int j2 = 0; j2 < 4; j2++) {
            float vlo, vhi;
            unpk(c2[ii][j2], vlo, vhi);
#pragma unroll
            for (int half = 0; half < 2; half++) {
                int n = bn * 128 + tx * 8 + 2 * j2 + half;
                int part = n >> 8;
                int rem = n & 255;
                int head = rem >> 5, dh = rem & 31;
                size_t o = (((size_t)Bw * 8 + head) * NTOK + t) * DH + dh;
                float v = half ? vhi : vlo;
                if (part == 0)      g_Q[o] = v * QSCALE;
                else if (part == 1) g_K[o] = v;
                else                g_V[o] = v;
            }
        }
    }
}

// ======================================================================
// 3) Attention: 4 query rows/warp, f32x2 packed over the reduction axis
//    (d-pairs in QK, j-pairs in AV via transposed V). 2 blocks/SM.
// ======================================================================
#define KSTR 36
#define VTSTR 324   // transposed V row stride (conflict-free LDS.128)
__global__ __launch_bounds__(256, 2) void attn_kernel() {
    int bh = blockIdx.x;            // Bw*8 + h
    int h = bh & 7;
    extern __shared__ float sm[];
    float* Ks = sm;                       // 294*36   = 10584
    float* Vt = Ks + NTOK * KSTR;         // 32*324   = 10368 (V transposed)
    float* Ps = Vt + DH * VTSTR;          // 8*256    =  2048 (dbl-buf 4x32/warp)
    float* Qr = Ps + 8 * 256;             // 8*128    =  1024
    // total 24024 floats = 93.8 KB -> 2 blocks/SM

    const float* Kg = g_K + (size_t)bh * NTOK * DH;
    const float* Vg = g_V + (size_t)bh * NTOK * DH;
    const float* Qg = g_Q + (size_t)bh * NTOK * DH;
    const float* Bb = g_bias + (size_t)h * NTOK * NTOK;

    int tid = threadIdx.x;
    for (int idx = tid; idx < NTOK * DH; idx += 256) {
        int j = idx >> 5, d = idx & 31;
        Ks[j * KSTR + d] = Kg[idx];
    }
    // V transposed: Vt[d][j], zero-padded to j<320
    for (int idx = tid; idx < 320 * DH; idx += 256) {
        int d = idx & 31, j = idx >> 5;
        Vt[d * VTSTR + j] = (j < NTOK) ? Vg[j * DH + d] : 0.f;
    }
    __syncthreads();

    int w = tid >> 5, lane = tid & 31;
    float* Pw = Ps + w * 256;             // two 128-float buffers
    float* Qw = Qr + w * 4 * DH;

    for (int i0 = w * 4; i0 < NTOK; i0 += 32) {
        // stage 4 q rows into smem
#pragma unroll
        for (int r = 0; r < 4; r++) {
            int i = i0 + r; if (i >= NTOK) i = NTOK - 1;
            Qw[r * DH + lane] = Qg[i * DH + lane];
        }
        __syncwarp();

        float s[4][10];

        // QK^T in two 5-strip halves (keeps accumulator pressure low).
        // Packed over d: s2 halves hold (even-d, odd-d) partial sums.
#pragma unroll
        for (int half = 0; half < 2; half++) {
            const float* kp[5];
#pragma unroll
            for (int jj = 0; jj < 5; jj++) {
                int j = lane + (half * 5 + jj) * 32;
                kp[jj] = Ks + (j < NTOK ? j : NTOK - 1) * KSTR;
            }
            u64 s2[4][5];
#pragma unroll
            for (int r = 0; r < 4; r++) {
                int i = i0 + r; if (i >= NTOK) i = NTOK - 1;
                const float* bi = Bb + (size_t)i * NTOK;
#pragma unroll
                for (int jj = 0; jj < 5; jj++) {
                    int j = lane + (half * 5 + jj) * 32;
                    // lo half carries bias (or -inf mask), hi half 0
                    s2[r][jj] = (u64)__float_as_uint(j < NTOK ? bi[j] : -1e30f);
                }
            }
#pragma unroll
            for (int d4 = 0; d4 < 8; d4++) {
                ulonglong2 q0 = *(const ulonglong2*)(Qw + 0 * DH + d4 * 4);
                ulonglong2 q1 = *(const ulonglong2*)(Qw + 1 * DH + d4 * 4);
                ulonglong2 q2 = *(const ulonglong2*)(Qw + 2 * DH + d4 * 4);
                ulonglong2 q3 = *(const ulonglong2*)(Qw + 3 * DH + d4 * 4);
#pragma unroll
                for (int jj = 0; jj < 5; jj++) {
                    ulonglong2 kv = *(const ulonglong2*)(kp[jj] + d4 * 4);
                    FMA2(s2[0][jj], q0.x, kv.x, s2[0][jj]);
                    FMA2(s2[0][jj], q0.y, kv.y, s2[0][jj]);
                    FMA2(s2[1][jj], q1.x, kv.x, s2[1][jj]);
                    FMA2(s2[1][jj], q1.y, kv.y, s2[1][jj]);
                    FMA2(s2[2][jj], q2.x, kv.x, s2[2][jj]);
                    FMA2(s2[2][jj], q2.y, kv.y, s2[2][jj]);
                    FMA2(s2[3][jj], q3.x, kv.x, s2[3][jj]);
                    FMA2(s2[3][jj], q3.y, kv.y, s2[3][jj]);
                }
            }
#pragma unroll
            for (int r = 0; r < 4; r++)
#pragma unroll
                for (int jj = 0; jj < 5; jj++)
                    s[r][half * 5 + jj] = foldadd(s2[r][jj]);
        }

        // softmax per row (OOB j -> exp(-1e30-mx) = 0)
        float inv[4];
#pragma unroll
        for (int r = 0; r < 4; r++) {
            float mx = -1e30f;
#pragma unroll
            for (int jj = 0; jj < 10; jj++) mx = fmaxf(mx, s[r][jj]);
#pragma unroll
            for (int o = 16; o > 0; o >>= 1)
                mx = fmaxf(mx, __shfl_xor_sync(0xffffffffu, mx, o));
            float sum = 0.f;
#pragma unroll
            for (int jj = 0; jj < 10; jj++) {
                float e = __expf(s[r][jj] - mx);
                s[r][jj] = e;
                sum += e;
            }
#pragma unroll
            for (int o = 16; o > 0; o >>= 1)
                sum += __shfl_xor_sync(0xffffffffu, sum, o);
            inv[r] = 1.f / sum;
        }

        // strip-wise A*V, packed over j-pairs via transposed V
        u64 acc2[4] = {0ULL, 0ULL, 0ULL, 0ULL};
        const float* vrow = Vt + lane * VTSTR;
#pragma unroll
        for (int jj = 0; jj < 10; jj++) {
            float* Pb = Pw + (jj & 1) * 128;
            Pb[0 * 32 + lane] = s[0][jj];
            Pb[1 * 32 + lane] = s[1][jj];
            Pb[2 * 32 + lane] = s[2][jj];
            Pb[3 * 32 + lane] = s[3][jj];
            __syncwarp();
            const float* vs = vrow + jj * 32;
#pragma unroll
            for (int m4 = 0; m4 < 8; m4++) {
                ulonglong2 vv = *(const ulonglong2*)(vs + m4 * 4);
                ulonglong2 p0 = *(const ulonglong2*)(Pb + 0 * 32 + m4 * 4);
                ulonglong2 p1 = *(const ulonglong2*)(Pb + 1 * 32 + m4 * 4);
                ulonglong2 p2 = *(const ulonglong2*)(Pb + 2 * 32 + m4 * 4);
                ulonglong2 p3 = *(const ulonglong2*)(Pb + 3 * 32 + m4 * 4);
                FMA2(acc2[0], p0.x, vv.x, acc2[0]);
                FMA2(acc2[0], p0.y, vv.y, acc2[0]);
                FMA2(acc2[1], p1.x, vv.x, acc2[1]);
                FMA2(acc2[1], p1.y, vv.y, acc2[1]);
                FMA2(acc2[2], p2.x, vv.x, acc2[2]);
                FMA2(acc2[2], p2.y, vv.y, acc2[2]);
                FMA2(acc2[3], p3.x, vv.x, acc2[3]);
                FMA2(acc2[3], p3.y, vv.y, acc2[3]);
            }
            __syncwarp();
        }

#pragma unroll
        for (int r = 0; r < 4; r++) {
            int i = i0 + r;
            if (i < NTOK)
                g_O[((size_t)bh * NTOK + i) * DH + lane] = foldadd(acc2[r]) * inv[r];
        }
        __syncwarp();
    }
}

// ======================================================================
// 4) Output projection (tiled SGEMM, f32x2, fused gather + scatter)
// ======================================================================
__global__ __launch_bounds__(256) void out_gemm(
    const float* __restrict__ w, float* __restrict__ out) {
    __shared__ float As[16][132];
    __shared__ float Bs[16][132];
    int tid = threadIdx.x;
    int bm = blockIdx.x, bn = blockIdx.y;

    int lrow = tid >> 2;
    int kq   = (tid & 3) << 2;

    int m0 = bm * 128 + lrow;
    int Bw0 = m0 / 294, t0 = m0 % 294;
    int m1 = m0 + 64;
    int Bw1 = m1 / 294, t1 = m1 % 294;

    const float* bp0 = w + (size_t)(bn * 128 + lrow) * 256;
    const float* bp1 = bp0 + (size_t)64 * 256;

    int tx = tid & 15, ty = tid >> 4;
    u64 c2[8][4];
#pragma unroll
    for (int i = 0; i < 8; i++)
#pragma unroll
        for (int j = 0; j < 4; j++) c2[i][j] = 0ULL;

    for (int k0 = 0; k0 < 256; k0 += 16) {
        int kk0 = k0 + kq;
        int head = kk0 >> 5, dh = kk0 & 31;
        const float* ap0 = g_O + (((size_t)Bw0 * 8 + head) * NTOK + t0) * DH + dh;
        const float* ap1 = g_O + (((size_t)Bw1 * 8 + head) * NTOK + t1) * DH + dh;
        float4 a0 = *(const float4*)ap0;
        float4 a1 = *(const float4*)ap1;
        float4 b0 = *(const float4*)(bp0 + k0 + kq);
        float4 b1 = *(const float4*)(bp1 + k0 + kq);
        __syncthreads();
        As[kq + 0][lrow] = a0.x; As[kq + 1][lrow] = a0.y;
        As[kq + 2][lrow] = a0.z; As[kq + 3][lrow] = a0.w;
        As[kq + 0][lrow + 64] = a1.x; As[kq + 1][lrow + 64] = a1.y;
        As[kq + 2][lrow + 64] = a1.z; As[kq + 3][lrow + 64] = a1.w;
        Bs[kq + 0][lrow] = b0.x; Bs[kq + 1][lrow] = b0.y;
        Bs[kq + 2][lrow] = b0.z; Bs[kq + 3][lrow] = b0.w;
        Bs[kq + 0][lrow + 64] = b1.x; Bs[kq + 1][lrow + 64] = b1.y;
        Bs[kq + 2][lrow + 64] = b1.z; Bs[kq + 3][lrow + 64] = b1.w;
        __syncthreads();
#pragma unroll
        for (int kk = 0; kk < 16; kk++) {
            u64 a2[8], bv2[4];
#pragma unroll
            for (int i = 0; i < 8; i++) a2[i] = pkdup(As[kk][ty * 8 + i]);
#pragma unroll
            for (int j = 0; j < 4; j++)
                bv2[j] = *(const u64*)(&Bs[kk][tx * 8 + 2 * j]);
#pragma unroll
            for (int i = 0; i < 8; i++)
#pragma unroll
                for (int j = 0; j < 4; j++)
                    FMA2(c2[i][j], a2[i], bv2[j], c2[i][j]);
        }
    }

#pragma unroll
    for (int ii = 0; ii < 8; ii++) {
        int m = bm * 128 + ty * 8 + ii;
        int Bw = m / 294, t = m % 294, l = t / 49, r = t % 49;
        float* op = out + ((size_t)((l * 256 + Bw) * 49 + r)) * 256 + bn * 128 + tx * 8;
        float c[8];
#pragma unroll
        for (int j2 = 0; j2 < 4; j2++) unpk(c2[ii][j2], c[2 * j2], c[2 * j2 + 1]);
        *(float4*)(op)     = make_float4(c[0], c[1], c[2], c[3]);
        *(float4*)(op + 4) = make_float4(c[4], c[5], c[6], c[7]);
    }
}

// ======================================================================
extern "C" void kernel_launch(void* const* d_in, const int* in_sizes, int n_in,
                              void* d_out, int out_size) {
    const float* x          = (const float*)d_in[0];
    const float* w_qkv      = (const float*)d_in[1];
    const float* w_out      = (const float*)d_in[2];
    const float* bias_table = (const float*)d_in[3];
    float* out = (float*)d_out;

    bias_kernel<<<NTOK, NTOK>>>(bias_table);
    qkv_gemm<<<dim3(588, 6), 256>>>(x, w_qkv);

    int smem = (NTOK * KSTR + DH * VTSTR + 8 * 256 + 8 * 128) * (int)sizeof(float);
    cudaFuncSetAttribute(attn_kernel, cudaFuncAttributeMaxDynamicSharedMemorySize, smem);
    attn_kernel<<<NWIN * NHEAD, 256, smem>>>();

    out_gemm<<<dim3(588, 2), 256>>>(w_out, out);
}

// round 7
// speedup vs baseline: 1.0022x; 1.0004x over previous
#include <cuda_runtime.h>
#include <cuda_bf16.h>
#include <math.h>

#define NTOK 294      // 6*7*7 tokens per window
#define NWIN 256      // 16*16 windows
#define NHEAD 8
#define DH 32
#define DIM 256
#define QSCALE 0.17677669529663687f  // 32^-0.5

typedef unsigned long long u64;

// packed fp32x2 FMA (Blackwell): d = a*b + c elementwise on 2 floats
#define FMA2(d, a, b, c) \
    asm("fma.rn.f32x2 %0, %1, %2, %3;" : "=l"(d) : "l"(a), "l"(b), "l"(c))

__device__ __forceinline__ u64 pkdup(float v) {
    u64 r; asm("mov.b64 %0, {%1, %1};" : "=l"(r) : "f"(v)); return r;
}
__device__ __forceinline__ float foldadd(u64 v) {
    float lo, hi; asm("mov.b64 {%0, %1}, %2;" : "=f"(lo), "=f"(hi) : "l"(v));
    return lo + hi;
}
__device__ __forceinline__ void unpk(u64 v, float& lo, float& hi) {
    asm("mov.b64 {%0, %1}, %2;" : "=f"(lo), "=f"(hi) : "l"(v));
}

// -------- scratch (device globals; no allocations allowed) --------
__device__ float g_Q[(size_t)NWIN*NHEAD*NTOK*DH];
__device__ float g_K[(size_t)NWIN*NHEAD*NTOK*DH];
__device__ float g_V[(size_t)NWIN*NHEAD*NTOK*DH];
__device__ float g_O[(size_t)NWIN*NHEAD*NTOK*DH];
__device__ float g_bias[(size_t)NHEAD*NTOK*NTOK];

// ======================================================================
// 1) Precompute relative position bias matrix bias[h][i][j]
// ======================================================================
__global__ void bias_kernel(const float* __restrict__ table) {
    int i = blockIdx.x;
    int j = threadIdx.x;
    int ai = i / 49, ri = i % 49, yi = ri / 7, xi = ri % 7;
    int aj = j / 49, rj = j % 49, yj = rj / 7, xj = rj % 7;
    int idx = (ai - aj + 5) * 169 + (yi - yj + 6) * 13 + (xi - xj + 6);
#pragma unroll
    for (int h = 0; h < NHEAD; h++)
        g_bias[((size_t)h * NTOK + i) * NTOK + j] = table[idx * NHEAD + h];
}

// ======================================================================
// 2) QKV projection (tiled SGEMM, f32x2 inner product, fused scatter)
// ======================================================================
__global__ __launch_bounds__(256) void qkv_gemm(
    const float* __restrict__ x, const float* __restrict__ w) {
    __shared__ float As[16][132];
    __shared__ float Bs[16][132];
    int tid = threadIdx.x;
    int bm = blockIdx.x, bn = blockIdx.y;

    int lrow = tid >> 2;            // 0..63
    int kq   = (tid & 3) << 2;      // 0,4,8,12

    const float *ap0, *ap1;
    {
        int m0 = bm * 128 + lrow;
        int Bw = m0 / 294, t = m0 % 294, l = t / 49, r = t % 49;
        ap0 = x + ((size_t)((l * 256 + Bw) * 49 + r)) * 256;
        int m1 = m0 + 64;
        Bw = m1 / 294; t = m1 % 294; l = t / 49; r = t % 49;
        ap1 = x + ((size_t)((l * 256 + Bw) * 49 + r)) * 256;
    }
    const float* bp0 = w + (size_t)(bn * 128 + lrow) * 256;
    const float* bp1 = bp0 + (size_t)64 * 256;

    int tx = tid & 15, ty = tid >> 4;
    u64 c2[8][4];
#pragma unroll
    for (int i = 0; i < 8; i++)
#pragma unroll
        for (int j = 0; j < 4; j++) c2[i][j] = 0ULL;

    for (int k0 = 0; k0 < 256; k0 += 16) {
        float4 a0 = *(const float4*)(ap0 + k0 + kq);
        float4 a1 = *(const float4*)(ap1 + k0 + kq);
        float4 b0 = *(const float4*)(bp0 + k0 + kq);
        float4 b1 = *(const float4*)(bp1 + k0 + kq);
        __syncthreads();
        As[kq + 0][lrow] = a0.x; As[kq + 1][lrow] = a0.y;
        As[kq + 2][lrow] = a0.z; As[kq + 3][lrow] = a0.w;
        As[kq + 0][lrow + 64] = a1.x; As[kq + 1][lrow + 64] = a1.y;
        As[kq + 2][lrow + 64] = a1.z; As[kq + 3][lrow + 64] = a1.w;
        Bs[kq + 0][lrow] = b0.x; Bs[kq + 1][lrow] = b0.y;
        Bs[kq + 2][lrow] = b0.z; Bs[kq + 3][lrow] = b0.w;
        Bs[kq + 0][lrow + 64] = b1.x; Bs[kq + 1][lrow + 64] = b1.y;
        Bs[kq + 2][lrow + 64] = b1.z; Bs[kq + 3][lrow + 64] = b1.w;
        __syncthreads();
#pragma unroll
        for (int kk = 0; kk < 16; kk++) {
            u64 a2[8], bv2[4];
#pragma unroll
            for (int i = 0; i < 8; i++) a2[i] = pkdup(As[kk][ty * 8 + i]);
#pragma unroll
            for (int j = 0; j < 4; j++)
                bv2[j] = *(const u64*)(&Bs[kk][tx * 8 + 2 * j]);
#pragma unroll
            for (int i = 0; i < 8; i++)
#pragma unroll
                for (int j = 0; j < 4; j++)
                    FMA2(c2[i][j], a2[i], bv2[j], c2[i][j]);
        }
    }

#pragma unroll
    for (int ii = 0; ii < 8; ii++) {
        int m = bm * 128 + ty * 8 + ii;
        int Bw = m / 294, t = m % 294;
#pragma unroll
        for (int j2 = 0; j2 < 4; j2++) {
            float vlo, vhi;
            unpk(c2[ii][j2], vlo, vhi);
#pragma unroll
            for (int half = 0; half < 2; half++) {
                int n = bn * 128 + tx * 8 + 2 * j2 + half;
                int part = n >> 8;
                int rem = n & 255;
                int head = rem >> 5, dh = rem & 31;
                size_t o = (((size_t)Bw * 8 + head) * NTOK + t) * DH + dh;
                float v = half ? vhi : vlo;
                if (part == 0)      g_Q[o] = v * QSCALE;
                else if (part == 1) g_K[o] = v;
                else                g_V[o] = v;
            }
        }
    }
}

// ======================================================================
// 3) Attention: 4 query rows/warp, f32x2 packed over the reduction axis
//    (d-pairs in QK, j-pairs in AV via transposed V). 2 blocks/SM.
// ======================================================================
#define KSTR 36
#define VTSTR 324   // transposed V row stride (conflict-free LDS.128)
__global__ __launch_bounds__(256, 2) void attn_kernel() {
    int bh = blockIdx.x;            // Bw*8 + h
    int h = bh & 7;
    extern __shared__ float sm[];
    float* Ks = sm;                       // 294*36   = 10584
    float* Vt = Ks + NTOK * KSTR;         // 32*324   = 10368 (V transposed)
    float* Ps = Vt + DH * VTSTR;          // 8*256    =  2048 (dbl-buf 4x32/warp)
    float* Qr = Ps + 8 * 256;             // 8*128    =  1024
    // total 24024 floats = 93.8 KB -> 2 blocks/SM

    const float* Kg = g_K + (size_t)bh * NTOK * DH;
    const float* Vg = g_V + (size_t)bh * NTOK * DH;
    const float* Qg = g_Q + (size_t)bh * NTOK * DH;
    const float* Bb = g_bias + (size_t)h * NTOK * NTOK;

    int tid = threadIdx.x;
    for (int idx = tid; idx < NTOK * DH; idx += 256) {
        int j = idx >> 5, d = idx & 31;
        Ks[j * KSTR + d] = Kg[idx];
    }
    // V transposed: Vt[d][j], zero-padded to j<320
    for (int idx = tid; idx < 320 * DH; idx += 256) {
        int d = idx & 31, j = idx >> 5;
        Vt[d * VTSTR + j] = (j < NTOK) ? Vg[j * DH + d] : 0.f;
    }
    __syncthreads();

    int w = tid >> 5, lane = tid & 31;
    float* Pw = Ps + w * 256;             // two 128-float buffers
    float* Qw = Qr + w * 4 * DH;

    for (int i0 = w * 4; i0 < NTOK; i0 += 32) {
        // stage 4 q rows into smem
#pragma unroll
        for (int r = 0; r < 4; r++) {
            int i = i0 + r; if (i >= NTOK) i = NTOK - 1;
            Qw[r * DH + lane] = Qg[i * DH + lane];
        }
        __syncwarp();

        float s[4][10];

        // QK^T in two 5-strip halves (keeps accumulator pressure low).
        // Packed over d: s2 halves hold (even-d, odd-d) partial sums.
#pragma unroll
        for (int half = 0; half < 2; half++) {
            const float* kp[5];
#pragma unroll
            for (int jj = 0; jj < 5; jj++) {
                int j = lane + (half * 5 + jj) * 32;
                kp[jj] = Ks + (j < NTOK ? j : NTOK - 1) * KSTR;
            }
            u64 s2[4][5];
#pragma unroll
            for (int r = 0; r < 4; r++) {
                int i = i0 + r; if (i >= NTOK) i = NTOK - 1;
                const float* bi = Bb + (size_t)i * NTOK;
#pragma unroll
                for (int jj = 0; jj < 5; jj++) {
                    int j = lane + (half * 5 + jj) * 32;
                    // lo half carries bias (or -inf mask), hi half 0
                    s2[r][jj] = (u64)__float_as_uint(j < NTOK ? bi[j] : -1e30f);
                }
            }
#pragma unroll
            for (int d4 = 0; d4 < 8; d4++) {
                ulonglong2 q0 = *(const ulonglong2*)(Qw + 0 * DH + d4 * 4);
                ulonglong2 q1 = *(const ulonglong2*)(Qw + 1 * DH + d4 * 4);
                ulonglong2 q2 = *(const ulonglong2*)(Qw + 2 * DH + d4 * 4);
                ulonglong2 q3 = *(const ulonglong2*)(Qw + 3 * DH + d4 * 4);
#pragma unroll
                for (int jj = 0; jj < 5; jj++) {
                    ulonglong2 kv = *(const ulonglong2*)(kp[jj] + d4 * 4);
                    FMA2(s2[0][jj], q0.x, kv.x, s2[0][jj]);
                    FMA2(s2[0][jj], q0.y, kv.y, s2[0][jj]);
                    FMA2(s2[1][jj], q1.x, kv.x, s2[1][jj]);
                    FMA2(s2[1][jj], q1.y, kv.y, s2[1][jj]);
                    FMA2(s2[2][jj], q2.x, kv.x, s2[2][jj]);
                    FMA2(s2[2][jj], q2.y, kv.y, s2[2][jj]);
                    FMA2(s2[3][jj], q3.x, kv.x, s2[3][jj]);
                    FMA2(s2[3][jj], q3.y, kv.y, s2[3][jj]);
                }
            }
#pragma unroll
            for (int r = 0; r < 4; r++)
#pragma unroll
                for (int jj = 0; jj < 5; jj++)
                    s[r][half * 5 + jj] = foldadd(s2[r][jj]);
        }

        // softmax per row (OOB j -> exp(-1e30-mx) = 0)
        float inv[4];
#pragma unroll
        for (int r = 0; r < 4; r++) {
            float mx = -1e30f;
#pragma unroll
            for (int jj = 0; jj < 10; jj++) mx = fmaxf(mx, s[r][jj]);
#pragma unroll
            for (int o = 16; o > 0; o >>= 1)
                mx = fmaxf(mx, __shfl_xor_sync(0xffffffffu, mx, o));
            float sum = 0.f;
#pragma unroll
            for (int jj = 0; jj < 10; jj++) {
                float e = __expf(s[r][jj] - mx);
                s[r][jj] = e;
                sum += e;
            }
#pragma unroll
            for (int o = 16; o > 0; o >>= 1)
                sum += __shfl_xor_sync(0xffffffffu, sum, o);
            inv[r] = 1.f / sum;
        }

        // strip-wise A*V, packed over j-pairs via transposed V
        u64 acc2[4] = {0ULL, 0ULL, 0ULL, 0ULL};
        const float* vrow = Vt + lane * VTSTR;
#pragma unroll
        for (int jj = 0; jj < 10; jj++) {
            float* Pb = Pw + (jj & 1) * 128;
            Pb[0 * 32 + lane] = s[0][jj];
            Pb[1 * 32 + lane] = s[1][jj];
            Pb[2 * 32 + lane] = s[2][jj];
            Pb[3 * 32 + lane] = s[3][jj];
            __syncwarp();
            const float* vs = vrow + jj * 32;
#pragma unroll
            for (int m4 = 0; m4 < 8; m4++) {
                ulonglong2 vv = *(const ulonglong2*)(vs + m4 * 4);
                ulonglong2 p0 = *(const ulonglong2*)(Pb + 0 * 32 + m4 * 4);
                ulonglong2 p1 = *(const ulonglong2*)(Pb + 1 * 32 + m4 * 4);
                ulonglong2 p2 = *(const ulonglong2*)(Pb + 2 * 32 + m4 * 4);
                ulonglong2 p3 = *(const ulonglong2*)(Pb + 3 * 32 + m4 * 4);
                FMA2(acc2[0], p0.x, vv.x, acc2[0]);
                FMA2(acc2[0], p0.y, vv.y, acc2[0]);
                FMA2(acc2[1], p1.x, vv.x, acc2[1]);
                FMA2(acc2[1], p1.y, vv.y, acc2[1]);
                FMA2(acc2[2], p2.x, vv.x, acc2[2]);
                FMA2(acc2[2], p2.y, vv.y, acc2[2]);
                FMA2(acc2[3], p3.x, vv.x, acc2[3]);
                FMA2(acc2[3], p3.y, vv.y, acc2[3]);
            }
            __syncwarp();
        }

#pragma unroll
        for (int r = 0; r < 4; r++) {
            int i = i0 + r;
            if (i < NTOK)
                g_O[((size_t)bh * NTOK + i) * DH + lane] = foldadd(acc2[r]) * inv[r];
        }
        __syncwarp();
    }
}

// ======================================================================
// 4) Output projection (tiled SGEMM, f32x2, fused gather + scatter)
// ======================================================================
__global__ __launch_bounds__(256) void out_gemm(
    const float* __restrict__ w, float* __restrict__ out) {
    __shared__ float As[16][132];
    __shared__ float Bs[16][132];
    int tid = threadIdx.x;
    int bm = blockIdx.x, bn = blockIdx.y;

    int lrow = tid >> 2;
    int kq   = (tid & 3) << 2;

    int m0 = bm * 128 + lrow;
    int Bw0 = m0 / 294, t0 = m0 % 294;
    int m1 = m0 + 64;
    int Bw1 = m1 / 294, t1 = m1 % 294;

    const float* bp0 = w + (size_t)(bn * 128 + lrow) * 256;
    const float* bp1 = bp0 + (size_t)64 * 256;

    int tx = tid & 15, ty = tid >> 4;
    u64 c2[8][4];
#pragma unroll
    for (int i = 0; i < 8; i++)
#pragma unroll
        for (int j = 0; j < 4; j++) c2[i][j] = 0ULL;

    for (int k0 = 0; k0 < 256; k0 += 16) {
        int kk0 = k0 + kq;
        int head = kk0 >> 5, dh = kk0 & 31;
        const float* ap0 = g_O + (((size_t)Bw0 * 8 + head) * NTOK + t0) * DH + dh;
        const float* ap1 = g_O + (((size_t)Bw1 * 8 + head) * NTOK + t1) * DH + dh;
        float4 a0 = *(const float4*)ap0;
        float4 a1 = *(const float4*)ap1;
        float4 b0 = *(const float4*)(bp0 + k0 + kq);
        float4 b1 = *(const float4*)(bp1 + k0 + kq);
        __syncthreads();
        As[kq + 0][lrow] = a0.x; As[kq + 1][lrow] = a0.y;
        As[kq + 2][lrow] = a0.z; As[kq + 3][lrow] = a0.w;
        As[kq + 0][lrow + 64] = a1.x; As[kq + 1][lrow + 64] = a1.y;
        As[kq + 2][lrow + 64] = a1.z; As[kq + 3][lrow + 64] = a1.w;
        Bs[kq + 0][lrow] = b0.x; Bs[kq + 1][lrow] = b0.y;
        Bs[kq + 2][lrow] = b0.z; Bs[kq + 3][lrow] = b0.w;
        Bs[kq + 0][lrow + 64] = b1.x; Bs[kq + 1][lrow + 64] = b1.y;
        Bs[kq + 2][lrow + 64] = b1.z; Bs[kq + 3][lrow + 64] = b1.w;
        __syncthreads();
#pragma unroll
        for (int kk = 0; kk < 16; kk++) {
            u64 a2[8], bv2[4];
#pragma unroll
            for (int i = 0; i < 8; i++) a2[i] = pkdup(As[kk][ty * 8 + i]);
#pragma unroll
            for (int j = 0; j < 4; j++)
                bv2[j] = *(const u64*)(&Bs[kk][tx * 8 + 2 * j]);
#pragma unroll
            for (int i = 0; i < 8; i++)
#pragma unroll
                for (int j = 0; j < 4; j++)
                    FMA2(c2[i][j], a2[i], bv2[j], c2[i][j]);
        }
    }

#pragma unroll
    for (int ii = 0; ii < 8; ii++) {
        int m = bm * 128 + ty * 8 + ii;
        int Bw = m / 294, t = m % 294, l = t / 49, r = t % 49;
        float* op = out + ((size_t)((l * 256 + Bw) * 49 + r)) * 256 + bn * 128 + tx * 8;
        float c[8];
#pragma unroll
        for (int j2 = 0; j2 < 4; j2++) unpk(c2[ii][j2], c[2 * j2], c[2 * j2 + 1]);
        *(float4*)(op)     = make_float4(c[0], c[1], c[2], c[3]);
        *(float4*)(op + 4) = make_float4(c[4], c[5], c[6], c[7]);
    }
}

// ======================================================================
extern "C" void kernel_launch(void* const* d_in, const int* in_sizes, int n_in,
                              void* d_out, int out_size) {
    const float* x          = (const float*)d_in[0];
    const float* w_qkv      = (const float*)d_in[1];
    const float* w_out      = (const float*)d_in[2];
    const float* bias_table = (const float*)d_in[3];
    float* out = (float*)d_out;

    bias_kernel<<<NTOK, NTOK>>>(bias_table);
    qkv_gemm<<<dim3(588, 6), 256>>>(x, w_qkv);

    int smem = (NTOK * KSTR + DH * VTSTR + 8 * 256 + 8 * 128) * (int)sizeof(float);
    cudaFuncSetAttribute(attn_kernel, cudaFuncAttributeMaxDynamicSharedMemorySize, smem);
    attn_kernel<<<NWIN * NHEAD, 256, smem>>>();

    out_gemm<<<dim3(588, 2), 256>>>(w_out, out);
}

// round 8
// speedup vs baseline: 1.1158x; 1.1133x over previous
#include <cuda_runtime.h>
#include <cuda_bf16.h>
#include <math.h>

#define NTOK 294      // 6*7*7 tokens per window
#define NWIN 256      // 16*16 windows
#define NHEAD 8
#define DH 32
#define DIM 256
#define QSCALE 0.17677669529663687f  // 32^-0.5

// -------- scratch (device globals; no allocations allowed) --------
__device__ float g_Q[(size_t)NWIN*NHEAD*NTOK*DH];
__device__ float g_K[(size_t)NWIN*NHEAD*NTOK*DH];
__device__ float g_V[(size_t)NWIN*NHEAD*NTOK*DH];
__device__ float g_O[(size_t)NWIN*NHEAD*NTOK*DH];
__device__ float g_bias[(size_t)NHEAD*NTOK*NTOK];

// ======================================================================
// 1) Precompute relative position bias matrix bias[h][i][j]
// ======================================================================
__global__ void bias_kernel(const float* __restrict__ table) {
    int i = blockIdx.x;
    int j = threadIdx.x;
    int ai = i / 49, ri = i % 49, yi = ri / 7, xi = ri % 7;
    int aj = j / 49, rj = j % 49, yj = rj / 7, xj = rj % 7;
    int idx = (ai - aj + 5) * 169 + (yi - yj + 6) * 13 + (xi - xj + 6);
#pragma unroll
    for (int h = 0; h < NHEAD; h++)
        g_bias[((size_t)h * NTOK + i) * NTOK + j] = table[idx * NHEAD + h];
}

// ======================================================================
// 2) QKV projection (tiled SGEMM, software-pipelined LDG, fused scatter)
// ======================================================================
__global__ __launch_bounds__(256) void qkv_gemm(
    const float* __restrict__ x, const float* __restrict__ w) {
    __shared__ float As[16][132];
    __shared__ float Bs[16][132];
    int tid = threadIdx.x;
    int bm = blockIdx.x, bn = blockIdx.y;

    int lrow = tid >> 2;            // 0..63
    int kq   = (tid & 3) << 2;      // 0,4,8,12

    const float *ap0, *ap1;
    {
        int m0 = bm * 128 + lrow;
        int Bw = m0 / 294, t = m0 % 294, l = t / 49, r = t % 49;
        ap0 = x + ((size_t)((l * 256 + Bw) * 49 + r)) * 256;
        int m1 = m0 + 64;
        Bw = m1 / 294; t = m1 % 294; l = t / 49; r = t % 49;
        ap1 = x + ((size_t)((l * 256 + Bw) * 49 + r)) * 256;
    }
    const float* bp0 = w + (size_t)(bn * 128 + lrow) * 256;
    const float* bp1 = bp0 + (size_t)64 * 256;

    int tx = tid & 15, ty = tid >> 4;
    float c[8][8];
#pragma unroll
    for (int i = 0; i < 8; i++)
#pragma unroll
        for (int j = 0; j < 8; j++) c[i][j] = 0.f;

    // prefetch tile 0
    float4 a0 = *(const float4*)(ap0 + kq);
    float4 a1 = *(const float4*)(ap1 + kq);
    float4 b0 = *(const float4*)(bp0 + kq);
    float4 b1 = *(const float4*)(bp1 + kq);

    for (int k0 = 0; k0 < 256; k0 += 16) {
        __syncthreads();
        As[kq + 0][lrow] = a0.x; As[kq + 1][lrow] = a0.y;
        As[kq + 2][lrow] = a0.z; As[kq + 3][lrow] = a0.w;
        As[kq + 0][lrow + 64] = a1.x; As[kq + 1][lrow + 64] = a1.y;
        As[kq + 2][lrow + 64] = a1.z; As[kq + 3][lrow + 64] = a1.w;
        Bs[kq + 0][lrow] = b0.x; Bs[kq + 1][lrow] = b0.y;
        Bs[kq + 2][lrow] = b0.z; Bs[kq + 3][lrow] = b0.w;
        Bs[kq + 0][lrow + 64] = b1.x; Bs[kq + 1][lrow + 64] = b1.y;
        Bs[kq + 2][lrow + 64] = b1.z; Bs[kq + 3][lrow + 64] = b1.w;
        __syncthreads();
        if (k0 + 16 < 256) {    // prefetch next tile; latency hidden by compute
            a0 = *(const float4*)(ap0 + k0 + 16 + kq);
            a1 = *(const float4*)(ap1 + k0 + 16 + kq);
            b0 = *(const float4*)(bp0 + k0 + 16 + kq);
            b1 = *(const float4*)(bp1 + k0 + 16 + kq);
        }
#pragma unroll
        for (int kk = 0; kk < 16; kk++) {
            float av[8], bv[8];
#pragma unroll
            for (int i = 0; i < 8; i++) av[i] = As[kk][ty * 8 + i];
#pragma unroll
            for (int j = 0; j < 8; j++) bv[j] = Bs[kk][tx * 8 + j];
#pragma unroll
            for (int i = 0; i < 8; i++)
#pragma unroll
                for (int j = 0; j < 8; j++) c[i][j] += av[i] * bv[j];
        }
    }

#pragma unroll
    for (int ii = 0; ii < 8; ii++) {
        int m = bm * 128 + ty * 8 + ii;
        int Bw = m / 294, t = m % 294;
#pragma unroll
        for (int jj = 0; jj < 8; jj++) {
            int n = bn * 128 + tx * 8 + jj;
            int part = n >> 8;
            int rem = n & 255;
            int head = rem >> 5, dh = rem & 31;
            size_t o = (((size_t)Bw * 8 + head) * NTOK + t) * DH + dh;
            float v = c[ii][jj];
            if (part == 0)      g_Q[o] = v * QSCALE;
            else if (part == 1) g_K[o] = v;
            else                g_V[o] = v;
        }
    }
}

// ======================================================================
// 3) Attention: 4 query rows/warp, scalar FFMA (f32x2 reverted), AV via
//    transposed V (one LDS.128 covers 4 j's). 2 blocks/SM.
// ======================================================================
#define KSTR 36
#define VTSTR 324   // transposed V row stride (bank-stride 4: conflict-free)
__global__ __launch_bounds__(256, 2) void attn_kernel() {
    int bh = blockIdx.x;            // Bw*8 + h
    int h = bh & 7;
    extern __shared__ float sm[];
    float* Ks = sm;                       // 294*36   = 10584
    float* Vt = Ks + NTOK * KSTR;         // 32*324   = 10368 (V transposed)
    float* Ps = Vt + DH * VTSTR;          // 8*256    =  2048 (dbl-buf 4x32/warp)
    float* Qr = Ps + 8 * 256;             // 8*128    =  1024
    // total 24024 floats = 93.8 KB -> 2 blocks/SM

    const float* Kg = g_K + (size_t)bh * NTOK * DH;
    const float* Vg = g_V + (size_t)bh * NTOK * DH;
    const float* Qg = g_Q + (size_t)bh * NTOK * DH;
    const float* Bb = g_bias + (size_t)h * NTOK * NTOK;

    int tid = threadIdx.x;
    for (int idx = tid; idx < NTOK * DH; idx += 256) {
        int j = idx >> 5, d = idx & 31;
        Ks[j * KSTR + d] = Kg[idx];
    }
    // V transposed: Vt[d][j], zero-padded to j<320
    for (int idx = tid; idx < 320 * DH; idx += 256) {
        int d = idx & 31, j = idx >> 5;
        Vt[d * VTSTR + j] = (j < NTOK) ? Vg[j * DH + d] : 0.f;
    }
    __syncthreads();

    int w = tid >> 5, lane = tid & 31;
    float* Pw = Ps + w * 256;             // two 128-float buffers
    float* Qw = Qr + w * 4 * DH;

    // per-lane K strip pointers (clamped; OOB strips give e=0 via -1e30 bias)
    const float* kp[10];
#pragma unroll
    for (int jj = 0; jj < 10; jj++) {
        int j = lane + jj * 32;
        kp[jj] = Ks + (j < NTOK ? j : NTOK - 1) * KSTR;
    }

    for (int i0 = w * 4; i0 < NTOK; i0 += 32) {
        // stage 4 q rows into smem
#pragma unroll
        for (int r = 0; r < 4; r++) {
            int i = i0 + r; if (i >= NTOK) i = NTOK - 1;
            Qw[r * DH + lane] = Qg[i * DH + lane];
        }
        __syncwarp();

        // accumulators initialized with bias (hides LDG latency under QK)
        float s[4][10];
#pragma unroll
        for (int r = 0; r < 4; r++) {
            int i = i0 + r; if (i >= NTOK) i = NTOK - 1;
            const float* bi = Bb + (size_t)i * NTOK;
#pragma unroll
            for (int jj = 0; jj < 10; jj++) {
                int j = lane + jj * 32;
                s[r][jj] = (j < NTOK) ? bi[j] : -1e30f;
            }
        }

        // QK^T: per d4-step, 14 LDS.128 feed 160 FMA
#pragma unroll
        for (int d4 = 0; d4 < 8; d4++) {
            float4 q0 = *(const float4*)(Qw + 0 * DH + d4 * 4);
            float4 q1 = *(const float4*)(Qw + 1 * DH + d4 * 4);
            float4 q2 = *(const float4*)(Qw + 2 * DH + d4 * 4);
            float4 q3 = *(const float4*)(Qw + 3 * DH + d4 * 4);
#pragma unroll
            for (int jj = 0; jj < 10; jj++) {
                float4 kv = *(const float4*)(kp[jj] + d4 * 4);
                s[0][jj] += q0.x*kv.x + q0.y*kv.y + q0.z*kv.z + q0.w*kv.w;
                s[1][jj] += q1.x*kv.x + q1.y*kv.y + q1.z*kv.z + q1.w*kv.w;
                s[2][jj] += q2.x*kv.x + q2.y*kv.y + q2.z*kv.z + q2.w*kv.w;
                s[3][jj] += q3.x*kv.x + q3.y*kv.y + q3.z*kv.z + q3.w*kv.w;
            }
        }

        // softmax per row (e kept in s[][]; OOB j -> exp(-1e30-mx) = 0)
        float inv[4];
#pragma unroll
        for (int r = 0; r < 4; r++) {
            float mx = -1e30f;
#pragma unroll
            for (int jj = 0; jj < 10; jj++) mx = fmaxf(mx, s[r][jj]);
#pragma unroll
            for (int o = 16; o > 0; o >>= 1)
                mx = fmaxf(mx, __shfl_xor_sync(0xffffffffu, mx, o));
            float sum = 0.f;
#pragma unroll
            for (int jj = 0; jj < 10; jj++) {
                float e = __expf(s[r][jj] - mx);
                s[r][jj] = e;
                sum += e;
            }
#pragma unroll
            for (int o = 16; o > 0; o >>= 1)
                sum += __shfl_xor_sync(0xffffffffu, sum, o);
            inv[r] = 1.f / sum;
        }

        // strip-wise A*V: park 4x32 e-values in the dbl-buffered P patch;
        // V side is one LDS.128 per 4 j's (transposed layout).
        float acc0 = 0.f, acc1 = 0.f, acc2 = 0.f, acc3 = 0.f;
        const float* vrow = Vt + lane * VTSTR;
#pragma unroll
        for (int jj = 0; jj < 10; jj++) {
            float* Pb = Pw + (jj & 1) * 128;
            Pb[0 * 32 + lane] = s[0][jj];
            Pb[1 * 32 + lane] = s[1][jj];
            Pb[2 * 32 + lane] = s[2][jj];
            Pb[3 * 32 + lane] = s[3][jj];
            __syncwarp();
            const float* vs = vrow + jj * 32;
#pragma unroll
            for (int m4 = 0; m4 < 8; m4++) {
                float4 vv = *(const float4*)(vs + m4 * 4);
                float4 p0 = *(const float4*)(Pb + 0 * 32 + m4 * 4);
                float4 p1 = *(const float4*)(Pb + 1 * 32 + m4 * 4);
                float4 p2 = *(const float4*)(Pb + 2 * 32 + m4 * 4);
                float4 p3 = *(const float4*)(Pb + 3 * 32 + m4 * 4);
                acc0 += p0.x*vv.x + p0.y*vv.y + p0.z*vv.z + p0.w*vv.w;
                acc1 += p1.x*vv.x + p1.y*vv.y + p1.z*vv.z + p1.w*vv.w;
                acc2 += p2.x*vv.x + p2.y*vv.y + p2.z*vv.z + p2.w*vv.w;
                acc3 += p3.x*vv.x + p3.y*vv.y + p3.z*vv.z + p3.w*vv.w;
            }
            __syncwarp();   // protect buffer reuse (parity covers adjacent strip)
        }

        float accs[4] = {acc0, acc1, acc2, acc3};
#pragma unroll
        for (int r = 0; r < 4; r++) {
            int i = i0 + r;
            if (i < NTOK)
                g_O[((size_t)bh * NTOK + i) * DH + lane] = accs[r] * inv[r];
        }
        __syncwarp();
    }
}

// ======================================================================
// 4) Output projection (tiled SGEMM, pipelined LDG, fused gather+scatter)
// ======================================================================
__global__ __launch_bounds__(256) void out_gemm(
    const float* __restrict__ w, float* __restrict__ out) {
    __shared__ float As[16][132];
    __shared__ float Bs[16][132];
    int tid = threadIdx.x;
    int bm = blockIdx.x, bn = blockIdx.y;

    int lrow = tid >> 2;
    int kq   = (tid & 3) << 2;

    int m0 = bm * 128 + lrow;
    int Bw0 = m0 / 294, t0 = m0 % 294;
    int m1 = m0 + 64;
    int Bw1 = m1 / 294, t1 = m1 % 294;

    const float* bp0 = w + (size_t)(bn * 128 + lrow) * 256;
    const float* bp1 = bp0 + (size_t)64 * 256;

    int tx = tid & 15, ty = tid >> 4;
    float c[8][8];
#pragma unroll
    for (int i = 0; i < 8; i++)
#pragma unroll
        for (int j = 0; j < 8; j++) c[i][j] = 0.f;

    // A gather addresses for k-tile starting at k0
    auto lda0 = [&](int k0) {
        int kk0 = k0 + kq; int head = kk0 >> 5, dh = kk0 & 31;
        return *(const float4*)(g_O + (((size_t)Bw0 * 8 + head) * NTOK + t0) * DH + dh);
    };
    auto lda1 = [&](int k0) {
        int kk0 = k0 + kq; int head = kk0 >> 5, dh = kk0 & 31;
        return *(const float4*)(g_O + (((size_t)Bw1 * 8 + head) * NTOK + t1) * DH + dh);
    };

    float4 a0 = lda0(0);
    float4 a1 = lda1(0);
    float4 b0 = *(const float4*)(bp0 + kq);
    float4 b1 = *(const float4*)(bp1 + kq);

    for (int k0 = 0; k0 < 256; k0 += 16) {
        __syncthreads();
        As[kq + 0][lrow] = a0.x; As[kq + 1][lrow] = a0.y;
        As[kq + 2][lrow] = a0.z; As[kq + 3][lrow] = a0.w;
        As[kq + 0][lrow + 64] = a1.x; As[kq + 1][lrow + 64] = a1.y;
        As[kq + 2][lrow + 64] = a1.z; As[kq + 3][lrow + 64] = a1.w;
        Bs[kq + 0][lrow] = b0.x; Bs[kq + 1][lrow] = b0.y;
        Bs[kq + 2][lrow] = b0.z; Bs[kq + 3][lrow] = b0.w;
        Bs[kq + 0][lrow + 64] = b1.x; Bs[kq + 1][lrow + 64] = b1.y;
        Bs[kq + 2][lrow + 64] = b1.z; Bs[kq + 3][lrow + 64] = b1.w;
        __syncthreads();
        if (k0 + 16 < 256) {
            a0 = lda0(k0 + 16);
            a1 = lda1(k0 + 16);
            b0 = *(const float4*)(bp0 + k0 + 16 + kq);
            b1 = *(const float4*)(bp1 + k0 + 16 + kq);
        }
#pragma unroll
        for (int kk = 0; kk < 16; kk++) {
            float av[8], bv[8];
#pragma unroll
            for (int i = 0; i < 8; i++) av[i] = As[kk][ty * 8 + i];
#pragma unroll
            for (int j = 0; j < 8; j++) bv[j] = Bs[kk][tx * 8 + j];
#pragma unroll
            for (int i = 0; i < 8; i++)
#pragma unroll
                for (int j = 0; j < 8; j++) c[i][j] += av[i] * bv[j];
        }
    }

#pragma unroll
    for (int ii = 0; ii < 8; ii++) {
        int m = bm * 128 + ty * 8 + ii;
        int Bw = m / 294, t = m % 294, l = t / 49, r = t % 49;
        float* op = out + ((size_t)((l * 256 + Bw) * 49 + r)) * 256 + bn * 128 + tx * 8;
        float4 v0 = make_float4(c[ii][0], c[ii][1], c[ii][2], c[ii][3]);
        float4 v1 = make_float4(c[ii][4], c[ii][5], c[ii][6], c[ii][7]);
        *(float4*)(op)     = v0;
        *(float4*)(op + 4) = v1;
    }
}

// ======================================================================
extern "C" void kernel_launch(void* const* d_in, const int* in_sizes, int n_in,
                              void* d_out, int out_size) {
    const float* x          = (const float*)d_in[0];
    const float* w_qkv      = (const float*)d_in[1];
    const float* w_out      = (const float*)d_in[2];
    const float* bias_table = (const float*)d_in[3];
    float* out = (float*)d_out;

    bias_kernel<<<NTOK, NTOK>>>(bias_table);
    qkv_gemm<<<dim3(588, 6), 256>>>(x, w_qkv);

    int smem = (NTOK * KSTR + DH * VTSTR + 8 * 256 + 8 * 128) * (int)sizeof(float);
    cudaFuncSetAttribute(attn_kernel, cudaFuncAttributeMaxDynamicSharedMemorySize, smem);
    attn_kernel<<<NWIN * NHEAD, 256, smem>>>();

    out_gemm<<<dim3(588, 2), 256>>>(w_out, out);
}

// round 9
// speedup vs baseline: 1.5341x; 1.3750x over previous
#include <cuda_runtime.h>
#include <cuda_bf16.h>
#include <math.h>

#define NTOK 294      // 6*7*7 tokens per window
#define NWIN 256      // 16*16 windows
#define NHEAD 8
#define DH 32
#define DIM 256
#define QSCALE 0.17677669529663687f  // 32^-0.5

// -------- scratch (device globals; no allocations allowed) --------
__device__ float g_Q[(size_t)NWIN*NHEAD*NTOK*DH];
__device__ float g_K[(size_t)NWIN*NHEAD*NTOK*DH];
__device__ float g_V[(size_t)NWIN*NHEAD*NTOK*DH];
__device__ float g_O[(size_t)NWIN*NHEAD*NTOK*DH];
__device__ float g_bias[(size_t)NHEAD*NTOK*NTOK];

// ---- tf32 helpers ----
__device__ __forceinline__ unsigned cvt_tf32(float f) {
    unsigned u; asm("cvt.rna.tf32.f32 %0, %1;" : "=r"(u) : "f"(f)); return u;
}
#define MMA8(D, A, B)                                                         \
    asm volatile(                                                             \
        "mma.sync.aligned.m16n8k8.row.col.f32.tf32.tf32.f32 "                 \
        "{%0,%1,%2,%3}, {%4,%5,%6,%7}, {%8,%9}, {%0,%1,%2,%3};"               \
        : "+f"((D)[0]), "+f"((D)[1]), "+f"((D)[2]), "+f"((D)[3])              \
        : "r"((A)[0]), "r"((A)[1]), "r"((A)[2]), "r"((A)[3]),                 \
          "r"((B)[0]), "r"((B)[1]))

// ======================================================================
// 1) Precompute relative position bias matrix bias[h][i][j]
// ======================================================================
__global__ void bias_kernel(const float* __restrict__ table) {
    int i = blockIdx.x;
    int j = threadIdx.x;
    int ai = i / 49, ri = i % 49, yi = ri / 7, xi = ri % 7;
    int aj = j / 49, rj = j % 49, yj = rj / 7, xj = rj % 7;
    int idx = (ai - aj + 5) * 169 + (yi - yj + 6) * 13 + (xi - xj + 6);
#pragma unroll
    for (int h = 0; h < NHEAD; h++)
        g_bias[((size_t)h * NTOK + i) * NTOK + j] = table[idx * NHEAD + h];
}

// ======================================================================
// 2) QKV projection: tf32 mma.sync, 128x128 tile, 8 warps (2m x 4n).
// ======================================================================
#define APAD 20     // A smem row stride: conflict-free fragment LDS
#define BPAD 136    // B smem row stride: conflict-free fragment LDS
__global__ __launch_bounds__(256, 2) void qkv_gemm(
    const float* __restrict__ x, const float* __restrict__ w) {
    __shared__ unsigned As[128][APAD];
    __shared__ unsigned Bs[16][BPAD];
    int tid = threadIdx.x;
    int bm = blockIdx.x, bn = blockIdx.y;
    int lrow = tid >> 2;            // 0..63
    int kq   = (tid & 3) << 2;      // 0,4,8,12

    const float *ap0, *ap1;
    {
        int m0 = bm * 128 + lrow;
        int Bw = m0 / 294, t = m0 % 294, l = t / 49, r = t % 49;
        ap0 = x + ((size_t)((l * 256 + Bw) * 49 + r)) * 256;
        int m1 = m0 + 64;
        Bw = m1 / 294; t = m1 % 294; l = t / 49; r = t % 49;
        ap1 = x + ((size_t)((l * 256 + Bw) * 49 + r)) * 256;
    }
    const float* bp0 = w + (size_t)(bn * 128 + lrow) * 256;
    const float* bp1 = bp0 + (size_t)64 * 256;

    int wid = tid >> 5, lane = tid & 31;
    int g = lane >> 2, lt = lane & 3;
    int m0w = (wid & 1) * 64, n0w = (wid >> 1) * 32;

    float acc[4][4][4];
#pragma unroll
    for (int a = 0; a < 4; a++)
#pragma unroll
        for (int b = 0; b < 4; b++)
#pragma unroll
            for (int c = 0; c < 4; c++) acc[a][b][c] = 0.f;

    float4 pa0 = *(const float4*)(ap0 + kq);
    float4 pa1 = *(const float4*)(ap1 + kq);
    float4 pb0 = *(const float4*)(bp0 + kq);
    float4 pb1 = *(const float4*)(bp1 + kq);

    for (int k0 = 0; k0 < 256; k0 += 16) {
        __syncthreads();
        *(uint4*)&As[lrow][kq] = make_uint4(
            cvt_tf32(pa0.x), cvt_tf32(pa0.y), cvt_tf32(pa0.z), cvt_tf32(pa0.w));
        *(uint4*)&As[lrow + 64][kq] = make_uint4(
            cvt_tf32(pa1.x), cvt_tf32(pa1.y), cvt_tf32(pa1.z), cvt_tf32(pa1.w));
        Bs[kq + 0][lrow] = cvt_tf32(pb0.x);
        Bs[kq + 1][lrow] = cvt_tf32(pb0.y);
        Bs[kq + 2][lrow] = cvt_tf32(pb0.z);
        Bs[kq + 3][lrow] = cvt_tf32(pb0.w);
        Bs[kq + 0][lrow + 64] = cvt_tf32(pb1.x);
        Bs[kq + 1][lrow + 64] = cvt_tf32(pb1.y);
        Bs[kq + 2][lrow + 64] = cvt_tf32(pb1.z);
        Bs[kq + 3][lrow + 64] = cvt_tf32(pb1.w);
        __syncthreads();
        if (k0 + 16 < 256) {
            pa0 = *(const float4*)(ap0 + k0 + 16 + kq);
            pa1 = *(const float4*)(ap1 + k0 + 16 + kq);
            pb0 = *(const float4*)(bp0 + k0 + 16 + kq);
            pb1 = *(const float4*)(bp1 + k0 + 16 + kq);
        }
#pragma unroll
        for (int k8 = 0; k8 < 16; k8 += 8) {
            unsigned af[4][4], bf[4][2];
#pragma unroll
            for (int mt = 0; mt < 4; mt++) {
                int rb = m0w + mt * 16 + g;
                af[mt][0] = As[rb][k8 + lt];
                af[mt][1] = As[rb + 8][k8 + lt];
                af[mt][2] = As[rb][k8 + lt + 4];
                af[mt][3] = As[rb + 8][k8 + lt + 4];
            }
#pragma unroll
            for (int nt = 0; nt < 4; nt++) {
                int cb = n0w + nt * 8 + g;
                bf[nt][0] = Bs[k8 + lt][cb];
                bf[nt][1] = Bs[k8 + lt + 4][cb];
            }
#pragma unroll
            for (int mt = 0; mt < 4; mt++)
#pragma unroll
                for (int nt = 0; nt < 4; nt++)
                    MMA8(acc[mt][nt], af[mt], bf[nt]);
        }
    }

    // epilogue: scatter into Q/K/V
#pragma unroll
    for (int mt = 0; mt < 4; mt++) {
#pragma unroll
        for (int half = 0; half < 2; half++) {
            int m = bm * 128 + m0w + mt * 16 + g + half * 8;
            int Bw = m / 294, tt = m % 294;
            size_t mb = (size_t)Bw * 8 * NTOK + tt;
#pragma unroll
            for (int nt = 0; nt < 4; nt++) {
#pragma unroll
                for (int e = 0; e < 2; e++) {
                    int n = bn * 128 + n0w + nt * 8 + 2 * lt + e;
                    int part = n >> 8, rem = n & 255;
                    int head = rem >> 5, dh = rem & 31;
                    size_t o = (mb + (size_t)head * NTOK) * DH + dh;
                    float v = acc[mt][nt][half * 2 + e];
                    if (part == 0)      g_Q[o] = v * QSCALE;
                    else if (part == 1) g_K[o] = v;
                    else                g_V[o] = v;
                }
            }
        }
    }
}

// ======================================================================
// 3) Attention (unchanged from R8): 4 q-rows/warp, transposed-V AV,
//    2 blocks/SM, fp32 throughout.
// ======================================================================
#define KSTR 36
#define VTSTR 324
__global__ __launch_bounds__(256, 2) void attn_kernel() {
    int bh = blockIdx.x;            // Bw*8 + h
    int h = bh & 7;
    extern __shared__ float sm[];
    float* Ks = sm;                       // 294*36
    float* Vt = Ks + NTOK * KSTR;         // 32*324 (V transposed)
    float* Ps = Vt + DH * VTSTR;          // 8*256 (dbl-buf 4x32/warp)
    float* Qr = Ps + 8 * 256;             // 8*128

    const float* Kg = g_K + (size_t)bh * NTOK * DH;
    const float* Vg = g_V + (size_t)bh * NTOK * DH;
    const float* Qg = g_Q + (size_t)bh * NTOK * DH;
    const float* Bb = g_bias + (size_t)h * NTOK * NTOK;

    int tid = threadIdx.x;
    for (int idx = tid; idx < NTOK * DH; idx += 256) {
        int j = idx >> 5, d = idx & 31;
        Ks[j * KSTR + d] = Kg[idx];
    }
    for (int idx = tid; idx < 320 * DH; idx += 256) {
        int d = idx & 31, j = idx >> 5;
        Vt[d * VTSTR + j] = (j < NTOK) ? Vg[j * DH + d] : 0.f;
    }
    __syncthreads();

    int w = tid >> 5, lane = tid & 31;
    float* Pw = Ps + w * 256;
    float* Qw = Qr + w * 4 * DH;

    const float* kp[10];
#pragma unroll
    for (int jj = 0; jj < 10; jj++) {
        int j = lane + jj * 32;
        kp[jj] = Ks + (j < NTOK ? j : NTOK - 1) * KSTR;
    }

    for (int i0 = w * 4; i0 < NTOK; i0 += 32) {
#pragma unroll
        for (int r = 0; r < 4; r++) {
            int i = i0 + r; if (i >= NTOK) i = NTOK - 1;
            Qw[r * DH + lane] = Qg[i * DH + lane];
        }
        __syncwarp();

        float s[4][10];
#pragma unroll
        for (int r = 0; r < 4; r++) {
            int i = i0 + r; if (i >= NTOK) i = NTOK - 1;
            const float* bi = Bb + (size_t)i * NTOK;
#pragma unroll
            for (int jj = 0; jj < 10; jj++) {
                int j = lane + jj * 32;
                s[r][jj] = (j < NTOK) ? bi[j] : -1e30f;
            }
        }

#pragma unroll
        for (int d4 = 0; d4 < 8; d4++) {
            float4 q0 = *(const float4*)(Qw + 0 * DH + d4 * 4);
            float4 q1 = *(const float4*)(Qw + 1 * DH + d4 * 4);
            float4 q2 = *(const float4*)(Qw + 2 * DH + d4 * 4);
            float4 q3 = *(const float4*)(Qw + 3 * DH + d4 * 4);
#pragma unroll
            for (int jj = 0; jj < 10; jj++) {
                float4 kv = *(const float4*)(kp[jj] + d4 * 4);
                s[0][jj] += q0.x*kv.x + q0.y*kv.y + q0.z*kv.z + q0.w*kv.w;
                s[1][jj] += q1.x*kv.x + q1.y*kv.y + q1.z*kv.z + q1.w*kv.w;
                s[2][jj] += q2.x*kv.x + q2.y*kv.y + q2.z*kv.z + q2.w*kv.w;
                s[3][jj] += q3.x*kv.x + q3.y*kv.y + q3.z*kv.z + q3.w*kv.w;
            }
        }

        float inv[4];
#pragma unroll
        for (int r = 0; r < 4; r++) {
            float mx = -1e30f;
#pragma unroll
            for (int jj = 0; jj < 10; jj++) mx = fmaxf(mx, s[r][jj]);
#pragma unroll
            for (int o = 16; o > 0; o >>= 1)
                mx = fmaxf(mx, __shfl_xor_sync(0xffffffffu, mx, o));
            float sum = 0.f;
#pragma unroll
            for (int jj = 0; jj < 10; jj++) {
                float e = __expf(s[r][jj] - mx);
                s[r][jj] = e;
                sum += e;
            }
#pragma unroll
            for (int o = 16; o > 0; o >>= 1)
                sum += __shfl_xor_sync(0xffffffffu, sum, o);
            inv[r] = 1.f / sum;
        }

        float acc0 = 0.f, acc1 = 0.f, acc2 = 0.f, acc3 = 0.f;
        const float* vrow = Vt + lane * VTSTR;
#pragma unroll
        for (int jj = 0; jj < 10; jj++) {
            float* Pb = Pw + (jj & 1) * 128;
            Pb[0 * 32 + lane] = s[0][jj];
            Pb[1 * 32 + lane] = s[1][jj];
            Pb[2 * 32 + lane] = s[2][jj];
            Pb[3 * 32 + lane] = s[3][jj];
            __syncwarp();
            const float* vs = vrow + jj * 32;
#pragma unroll
            for (int m4 = 0; m4 < 8; m4++) {
                float4 vv = *(const float4*)(vs + m4 * 4);
                float4 p0 = *(const float4*)(Pb + 0 * 32 + m4 * 4);
                float4 p1 = *(const float4*)(Pb + 1 * 32 + m4 * 4);
                float4 p2 = *(const float4*)(Pb + 2 * 32 + m4 * 4);
                float4 p3 = *(const float4*)(Pb + 3 * 32 + m4 * 4);
                acc0 += p0.x*vv.x + p0.y*vv.y + p0.z*vv.z + p0.w*vv.w;
                acc1 += p1.x*vv.x + p1.y*vv.y + p1.z*vv.z + p1.w*vv.w;
                acc2 += p2.x*vv.x + p2.y*vv.y + p2.z*vv.z + p2.w*vv.w;
                acc3 += p3.x*vv.x + p3.y*vv.y + p3.z*vv.z + p3.w*vv.w;
            }
            __syncwarp();
        }

        float accs[4] = {acc0, acc1, acc2, acc3};
#pragma unroll
        for (int r = 0; r < 4; r++) {
            int i = i0 + r;
            if (i < NTOK)
                g_O[((size_t)bh * NTOK + i) * DH + lane] = accs[r] * inv[r];
        }
        __syncwarp();
    }
}

// ======================================================================
// 4) Output projection: tf32 mma.sync, fused gather from g_O + scatter.
// ======================================================================
__global__ __launch_bounds__(256, 2) void out_gemm(
    const float* __restrict__ w, float* __restrict__ out) {
    __shared__ unsigned As[128][APAD];
    __shared__ unsigned Bs[16][BPAD];
    int tid = threadIdx.x;
    int bm = blockIdx.x, bn = blockIdx.y;
    int lrow = tid >> 2;
    int kq   = (tid & 3) << 2;

    int m0 = bm * 128 + lrow;
    int Bw0 = m0 / 294, t0 = m0 % 294;
    int m1 = m0 + 64;
    int Bw1 = m1 / 294, t1 = m1 % 294;
    const float* abase0 = g_O + ((size_t)Bw0 * 8 * NTOK + t0) * DH;
    const float* abase1 = g_O + ((size_t)Bw1 * 8 * NTOK + t1) * DH;

    const float* bp0 = w + (size_t)(bn * 128 + lrow) * 256;
    const float* bp1 = bp0 + (size_t)64 * 256;

    int wid = tid >> 5, lane = tid & 31;
    int g = lane >> 2, lt = lane & 3;
    int m0w = (wid & 1) * 64, n0w = (wid >> 1) * 32;

    float acc[4][4][4];
#pragma unroll
    for (int a = 0; a < 4; a++)
#pragma unroll
        for (int b = 0; b < 4; b++)
#pragma unroll
            for (int c = 0; c < 4; c++) acc[a][b][c] = 0.f;

    auto lda = [&](const float* base, int k) {
        int head = k >> 5, dh = k & 31;
        return *(const float4*)(base + (size_t)head * NTOK * DH + dh);
    };

    float4 pa0 = lda(abase0, kq);
    float4 pa1 = lda(abase1, kq);
    float4 pb0 = *(const float4*)(bp0 + kq);
    float4 pb1 = *(const float4*)(bp1 + kq);

    for (int k0 = 0; k0 < 256; k0 += 16) {
        __syncthreads();
        *(uint4*)&As[lrow][kq] = make_uint4(
            cvt_tf32(pa0.x), cvt_tf32(pa0.y), cvt_tf32(pa0.z), cvt_tf32(pa0.w));
        *(uint4*)&As[lrow + 64][kq] = make_uint4(
            cvt_tf32(pa1.x), cvt_tf32(pa1.y), cvt_tf32(pa1.z), cvt_tf32(pa1.w));
        Bs[kq + 0][lrow] = cvt_tf32(pb0.x);
        Bs[kq + 1][lrow] = cvt_tf32(pb0.y);
        Bs[kq + 2][lrow] = cvt_tf32(pb0.z);
        Bs[kq + 3][lrow] = cvt_tf32(pb0.w);
        Bs[kq + 0][lrow + 64] = cvt_tf32(pb1.x);
        Bs[kq + 1][lrow + 64] = cvt_tf32(pb1.y);
        Bs[kq + 2][lrow + 64] = cvt_tf32(pb1.z);
        Bs[kq + 3][lrow + 64] = cvt_tf32(pb1.w);
        __syncthreads();
        if (k0 + 16 < 256) {
            pa0 = lda(abase0, k0 + 16 + kq);
            pa1 = lda(abase1, k0 + 16 + kq);
            pb0 = *(const float4*)(bp0 + k0 + 16 + kq);
            pb1 = *(const float4*)(bp1 + k0 + 16 + kq);
        }
#pragma unroll
        for (int k8 = 0; k8 < 16; k8 += 8) {
            unsigned af[4][4], bf[4][2];
#pragma unroll
            for (int mt = 0; mt < 4; mt++) {
                int rb = m0w + mt * 16 + g;
                af[mt][0] = As[rb][k8 + lt];
                af[mt][1] = As[rb + 8][k8 + lt];
                af[mt][2] = As[rb][k8 + lt + 4];
                af[mt][3] = As[rb + 8][k8 + lt + 4];
            }
#pragma unroll
            for (int nt = 0; nt < 4; nt++) {
                int cb = n0w + nt * 8 + g;
                bf[nt][0] = Bs[k8 + lt][cb];
                bf[nt][1] = Bs[k8 + lt + 4][cb];
            }
#pragma unroll
            for (int mt = 0; mt < 4; mt++)
#pragma unroll
                for (int nt = 0; nt < 4; nt++)
                    MMA8(acc[mt][nt], af[mt], bf[nt]);
        }
    }

    // epilogue: scatter to output layout, float2 per (mt, half, nt)
#pragma unroll
    for (int mt = 0; mt < 4; mt++) {
#pragma unroll
        for (int half = 0; half < 2; half++) {
            int m = bm * 128 + m0w + mt * 16 + g + half * 8;
            int Bw = m / 294, tt = m % 294, l = tt / 49, r = tt % 49;
            float* op = out + ((size_t)((l * 256 + Bw) * 49 + r)) * 256;
#pragma unroll
            for (int nt = 0; nt < 4; nt++) {
                int n = bn * 128 + n0w + nt * 8 + 2 * lt;
                float2 v = make_float2(acc[mt][nt][half * 2],
                                       acc[mt][nt][half * 2 + 1]);
                *(float2*)(op + n) = v;
            }
        }
    }
}

// ======================================================================
extern "C" void kernel_launch(void* const* d_in, const int* in_sizes, int n_in,
                              void* d_out, int out_size) {
    const float* x          = (const float*)d_in[0];
    const float* w_qkv      = (const float*)d_in[1];
    const float* w_out      = (const float*)d_in[2];
    const float* bias_table = (const float*)d_in[3];
    float* out = (float*)d_out;

    bias_kernel<<<NTOK, NTOK>>>(bias_table);
    qkv_gemm<<<dim3(588, 6), 256>>>(x, w_qkv);

    int smem = (NTOK * KSTR + DH * VTSTR + 8 * 256 + 8 * 128) * (int)sizeof(float);
    cudaFuncSetAttribute(attn_kernel, cudaFuncAttributeMaxDynamicSharedMemorySize, smem);
    attn_kernel<<<NWIN * NHEAD, 256, smem>>>();

    out_gemm<<<dim3(588, 2), 256>>>(w_out, out);
}

// round 11
// speedup vs baseline: 1.8072x; 1.1780x over previous
#include <cuda_runtime.h>
#include <cuda_bf16.h>
#include <math.h>

#define NTOK 294      // 6*7*7 tokens per window
#define NWIN 256      // 16*16 windows
#define NHEAD 8
#define DH 32
#define DIM 256
#define QSCALE 0.17677669529663687f  // 32^-0.5

// -------- scratch (device globals; no allocations allowed) --------
__device__ float g_Q[(size_t)NWIN*NHEAD*NTOK*DH];
__device__ float g_K[(size_t)NWIN*NHEAD*NTOK*DH];
__device__ float g_V[(size_t)NWIN*NHEAD*NTOK*DH];
__device__ float g_O[(size_t)NWIN*NHEAD*NTOK*DH];
__device__ float g_bias[(size_t)NHEAD*NTOK*NTOK];

// ---- tf32 helpers ----
__device__ __forceinline__ unsigned cvt_tf32(float f) {
    unsigned u; asm("cvt.rna.tf32.f32 %0, %1;" : "=r"(u) : "f"(f)); return u;
}
#define MMA8(D, A, B)                                                         \
    asm volatile(                                                             \
        "mma.sync.aligned.m16n8k8.row.col.f32.tf32.tf32.f32 "                 \
        "{%0,%1,%2,%3}, {%4,%5,%6,%7}, {%8,%9}, {%0,%1,%2,%3};"               \
        : "+f"((D)[0]), "+f"((D)[1]), "+f"((D)[2]), "+f"((D)[3])              \
        : "r"((A)[0]), "r"((A)[1]), "r"((A)[2]), "r"((A)[3]),                 \
          "r"((B)[0]), "r"((B)[1]))

// ======================================================================
// 1) Precompute relative position bias matrix bias[h][i][j]
// ======================================================================
__global__ void bias_kernel(const float* __restrict__ table) {
    int i = blockIdx.x;
    int j = threadIdx.x;
    int ai = i / 49, ri = i % 49, yi = ri / 7, xi = ri % 7;
    int aj = j / 49, rj = j % 49, yj = rj / 7, xj = rj % 7;
    int idx = (ai - aj + 5) * 169 + (yi - yj + 6) * 13 + (xi - xj + 6);
#pragma unroll
    for (int h = 0; h < NHEAD; h++)
        g_bias[((size_t)h * NTOK + i) * NTOK + j] = table[idx * NHEAD + h];
}

// ======================================================================
// 2) QKV projection: tf32 mma.sync, 128x128 tile, 8 warps (2m x 4n).
// ======================================================================
#define APAD 20
#define BPAD 136
__global__ __launch_bounds__(256, 2) void qkv_gemm(
    const float* __restrict__ x, const float* __restrict__ w) {
    __shared__ unsigned As[128][APAD];
    __shared__ unsigned Bs[16][BPAD];
    int tid = threadIdx.x;
    int bm = blockIdx.x, bn = blockIdx.y;
    int lrow = tid >> 2;
    int kq   = (tid & 3) << 2;

    const float *ap0, *ap1;
    {
        int m0 = bm * 128 + lrow;
        int Bw = m0 / 294, t = m0 % 294, l = t / 49, r = t % 49;
        ap0 = x + ((size_t)((l * 256 + Bw) * 49 + r)) * 256;
        int m1 = m0 + 64;
        Bw = m1 / 294; t = m1 % 294; l = t / 49; r = t % 49;
        ap1 = x + ((size_t)((l * 256 + Bw) * 49 + r)) * 256;
    }
    const float* bp0 = w + (size_t)(bn * 128 + lrow) * 256;
    const float* bp1 = bp0 + (size_t)64 * 256;

    int wid = tid >> 5, lane = tid & 31;
    int g = lane >> 2, lt = lane & 3;
    int m0w = (wid & 1) * 64, n0w = (wid >> 1) * 32;

    float acc[4][4][4];
#pragma unroll
    for (int a = 0; a < 4; a++)
#pragma unroll
        for (int b = 0; b < 4; b++)
#pragma unroll
            for (int c = 0; c < 4; c++) acc[a][b][c] = 0.f;

    float4 pa0 = *(const float4*)(ap0 + kq);
    float4 pa1 = *(const float4*)(ap1 + kq);
    float4 pb0 = *(const float4*)(bp0 + kq);
    float4 pb1 = *(const float4*)(bp1 + kq);

    for (int k0 = 0; k0 < 256; k0 += 16) {
        __syncthreads();
        *(uint4*)&As[lrow][kq] = make_uint4(
            cvt_tf32(pa0.x), cvt_tf32(pa0.y), cvt_tf32(pa0.z), cvt_tf32(pa0.w));
        *(uint4*)&As[lrow + 64][kq] = make_uint4(
            cvt_tf32(pa1.x), cvt_tf32(pa1.y), cvt_tf32(pa1.z), cvt_tf32(pa1.w));
        Bs[kq + 0][lrow] = cvt_tf32(pb0.x);
        Bs[kq + 1][lrow] = cvt_tf32(pb0.y);
        Bs[kq + 2][lrow] = cvt_tf32(pb0.z);
        Bs[kq + 3][lrow] = cvt_tf32(pb0.w);
        Bs[kq + 0][lrow + 64] = cvt_tf32(pb1.x);
        Bs[kq + 1][lrow + 64] = cvt_tf32(pb1.y);
        Bs[kq + 2][lrow + 64] = cvt_tf32(pb1.z);
        Bs[kq + 3][lrow + 64] = cvt_tf32(pb1.w);
        __syncthreads();
        if (k0 + 16 < 256) {
            pa0 = *(const float4*)(ap0 + k0 + 16 + kq);
            pa1 = *(const float4*)(ap1 + k0 + 16 + kq);
            pb0 = *(const float4*)(bp0 + k0 + 16 + kq);
            pb1 = *(const float4*)(bp1 + k0 + 16 + kq);
        }
#pragma unroll
        for (int k8 = 0; k8 < 16; k8 += 8) {
            unsigned af[4][4], bf[4][2];
#pragma unroll
            for (int mt = 0; mt < 4; mt++) {
                int rb = m0w + mt * 16 + g;
                af[mt][0] = As[rb][k8 + lt];
                af[mt][1] = As[rb + 8][k8 + lt];
                af[mt][2] = As[rb][k8 + lt + 4];
                af[mt][3] = As[rb + 8][k8 + lt + 4];
            }
#pragma unroll
            for (int nt = 0; nt < 4; nt++) {
                int cb = n0w + nt * 8 + g;
                bf[nt][0] = Bs[k8 + lt][cb];
                bf[nt][1] = Bs[k8 + lt + 4][cb];
            }
#pragma unroll
            for (int mt = 0; mt < 4; mt++)
#pragma unroll
                for (int nt = 0; nt < 4; nt++)
                    MMA8(acc[mt][nt], af[mt], bf[nt]);
        }
    }

#pragma unroll
    for (int mt = 0; mt < 4; mt++) {
#pragma unroll
        for (int half = 0; half < 2; half++) {
            int m = bm * 128 + m0w + mt * 16 + g + half * 8;
            int Bw = m / 294, tt = m % 294;
            size_t mb = (size_t)Bw * 8 * NTOK + tt;
#pragma unroll
            for (int nt = 0; nt < 4; nt++) {
#pragma unroll
                for (int e = 0; e < 2; e++) {
                    int n = bn * 128 + n0w + nt * 8 + 2 * lt + e;
                    int part = n >> 8, rem = n & 255;
                    int head = rem >> 5, dh = rem & 31;
                    size_t o = (mb + (size_t)head * NTOK) * DH + dh;
                    float v = acc[mt][nt][half * 2 + e];
                    if (part == 0)      g_Q[o] = v * QSCALE;
                    else if (part == 1) g_K[o] = v;
                    else                g_V[o] = v;
                }
            }
        }
    }
}

// ======================================================================
// 3) Attention: full tf32 mma.sync. Per (window,head) block:
//    19 m-tiles of 16 q-rows; QK (warps split 38 n-tiles) -> softmax
//    (bias fused, P written back as tf32) -> AV (4 d-tiles x 2 k-halves
//    of 19 k8-chunks each = 38 total, smem pair reduction). 2 blocks/SM.
// ======================================================================
#define KSTR2 33     // K smem row stride (33g%32=g: conflict-free B frags)
#define VTSTR2 313   // Vt stride (25g%32 distinct: conflict-free B frags)
#define SSTR 316     // S/P stride (28g%32 distinct, even for STS.64)
#define JT 304       // j padded to 38 n-tiles of 8
__global__ __launch_bounds__(256, 2) void attn_kernel() {
    int bh = blockIdx.x;            // Bw*8 + h
    int h = bh & 7;
    extern __shared__ unsigned smu[];
    unsigned* Ks = smu;                    // 304*33  = 10032
    unsigned* Vt = Ks + JT * KSTR2;        // 32*313  = 10016
    float*    S  = (float*)(Vt + DH * VTSTR2);  // 16*316 = 5056 (S then P)
    float*    Red = S + 16 * SSTR;         // 512 (AV partial reduce)
    // total 25616 words = 102464 B

    const float* Kg = g_K + (size_t)bh * NTOK * DH;
    const float* Vg = g_V + (size_t)bh * NTOK * DH;
    const float* Qg = g_Q + (size_t)bh * NTOK * DH;
    const float* Bb = g_bias + (size_t)h * NTOK * NTOK;

    int tid = threadIdx.x;
    // load K (tf32, zero-padded rows) and V transposed (tf32, zero-padded)
    for (int idx = tid; idx < JT * DH; idx += 256) {
        int j = idx >> 5, d = idx & 31;
        float kv = (j < NTOK) ? Kg[j * DH + d] : 0.f;
        float vv = (j < NTOK) ? Vg[j * DH + d] : 0.f;
        Ks[j * KSTR2 + d] = cvt_tf32(kv);
        Vt[d * VTSTR2 + j] = cvt_tf32(vv);
    }
    __syncthreads();

    int w = tid >> 5, lane = tid & 31;
    int g = lane >> 2, lt = lane & 3;
    int srow = tid >> 4, scol = tid & 15;   // softmax mapping: 16 thr/row
    int dt = w & 3, khalf = w >> 2;         // AV mapping

    for (int it = 0; it < 19; it++) {
        int i0 = it * 16;

        // ---- Q A-fragments (same for all warps; direct LDG, L1-hot) ----
        int r0 = i0 + g;     if (r0 >= NTOK) r0 = NTOK - 1;
        int r1 = i0 + g + 8; if (r1 >= NTOK) r1 = NTOK - 1;
        unsigned qf[4][4];
#pragma unroll
        for (int k8 = 0; k8 < 4; k8++) {
            qf[k8][0] = cvt_tf32(Qg[r0 * DH + k8 * 8 + lt]);
            qf[k8][1] = cvt_tf32(Qg[r1 * DH + k8 * 8 + lt]);
            qf[k8][2] = cvt_tf32(Qg[r0 * DH + k8 * 8 + lt + 4]);
            qf[k8][3] = cvt_tf32(Qg[r1 * DH + k8 * 8 + lt + 4]);
        }

        // ---- QK^T: warp w does n-tiles w, w+8, ... ----
        for (int nt = w; nt < 38; nt += 8) {
            float acc[4] = {0.f, 0.f, 0.f, 0.f};
            const unsigned* kb = Ks + (nt * 8 + g) * KSTR2;
#pragma unroll
            for (int k8 = 0; k8 < 4; k8++) {
                unsigned bf[2] = { kb[k8 * 8 + lt], kb[k8 * 8 + lt + 4] };
                MMA8(acc, qf[k8], bf);
            }
            *(float2*)(S + g * SSTR + nt * 8 + 2 * lt) =
                make_float2(acc[0], acc[1]);
            *(float2*)(S + (g + 8) * SSTR + nt * 8 + 2 * lt) =
                make_float2(acc[2], acc[3]);
        }
        __syncthreads();

        // ---- softmax + bias; write P back as tf32 ----
        {
            int ig = i0 + srow; if (ig >= NTOK) ig = NTOK - 1;
            const float* brow = Bb + (size_t)ig * NTOK;
            float* Srow = S + srow * SSTR;
            float f[19];
            float mx = -1e30f;
#pragma unroll
            for (int k = 0; k < 19; k++) {
                int c = scol + 16 * k;
                float v = (c < NTOK) ? (Srow[c] + brow[c]) : -1e30f;
                f[k] = v;
                mx = fmaxf(mx, v);
            }
#pragma unroll
            for (int o = 1; o < 16; o <<= 1)
                mx = fmaxf(mx, __shfl_xor_sync(0xffffffffu, mx, o));
            float sum = 0.f;
#pragma unroll
            for (int k = 0; k < 19; k++) {
                float e = __expf(f[k] - mx);
                f[k] = e;
                sum += e;
            }
#pragma unroll
            for (int o = 1; o < 16; o <<= 1)
                sum += __shfl_xor_sync(0xffffffffu, sum, o);
            float inv = 1.f / sum;
            unsigned* Prow = (unsigned*)Srow;
#pragma unroll
            for (int k = 0; k < 19; k++)
                Prow[scol + 16 * k] = cvt_tf32(f[k] * inv);
        }
        __syncthreads();

        // ---- AV: P[16x304] x V[304x32]; warp = (d-tile, k-half) ----
        // 38 k8-chunks total; each k-half covers 19.
        {
            float acc[4] = {0.f, 0.f, 0.f, 0.f};
            const unsigned* SP = (const unsigned*)S;
            const unsigned* vb = Vt + (dt * 8 + g) * VTSTR2;
            int kbeg = khalf * 19, kend = kbeg + 19;
            for (int kc = kbeg; kc < kend; kc++) {
                int j0 = kc * 8;
                unsigned af[4] = {
                    SP[g * SSTR + j0 + lt], SP[(g + 8) * SSTR + j0 + lt],
                    SP[g * SSTR + j0 + lt + 4], SP[(g + 8) * SSTR + j0 + lt + 4] };
                unsigned bf[2] = { vb[j0 + lt], vb[j0 + lt + 4] };
                MMA8(acc, af, bf);
            }
            if (khalf) {
                float* rp = Red + dt * 128;
                *(float2*)(rp + g * 8 + 2 * lt) = make_float2(acc[0], acc[1]);
                *(float2*)(rp + (g + 8) * 8 + 2 * lt) = make_float2(acc[2], acc[3]);
            }
            __syncthreads();
            if (!khalf) {
                const float* rp = Red + dt * 128;
                float2 r01 = *(const float2*)(rp + g * 8 + 2 * lt);
                float2 r23 = *(const float2*)(rp + (g + 8) * 8 + 2 * lt);
                acc[0] += r01.x; acc[1] += r01.y;
                acc[2] += r23.x; acc[3] += r23.y;
                float* ob = g_O + (size_t)bh * NTOK * DH;
                int ia = i0 + g, ib = i0 + g + 8;
                if (ia < NTOK)
                    *(float2*)(ob + ia * DH + dt * 8 + 2 * lt) =
                        make_float2(acc[0], acc[1]);
                if (ib < NTOK)
                    *(float2*)(ob + ib * DH + dt * 8 + 2 * lt) =
                        make_float2(acc[2], acc[3]);
            }
        }
    }
}

// ======================================================================
// 4) Output projection: tf32 mma.sync, fused gather from g_O + scatter.
// ======================================================================
__global__ __launch_bounds__(256, 2) void out_gemm(
    const float* __restrict__ w, float* __restrict__ out) {
    __shared__ unsigned As[128][APAD];
    __shared__ unsigned Bs[16][BPAD];
    int tid = threadIdx.x;
    int bm = blockIdx.x, bn = blockIdx.y;
    int lrow = tid >> 2;
    int kq   = (tid & 3) << 2;

    int m0 = bm * 128 + lrow;
    int Bw0 = m0 / 294, t0 = m0 % 294;
    int m1 = m0 + 64;
    int Bw1 = m1 / 294, t1 = m1 % 294;
    const float* abase0 = g_O + ((size_t)Bw0 * 8 * NTOK + t0) * DH;
    const float* abase1 = g_O + ((size_t)Bw1 * 8 * NTOK + t1) * DH;

    const float* bp0 = w + (size_t)(bn * 128 + lrow) * 256;
    const float* bp1 = bp0 + (size_t)64 * 256;

    int wid = tid >> 5, lane = tid & 31;
    int g = lane >> 2, lt = lane & 3;
    int m0w = (wid & 1) * 64, n0w = (wid >> 1) * 32;

    float acc[4][4][4];
#pragma unroll
    for (int a = 0; a < 4; a++)
#pragma unroll
        for (int b = 0; b < 4; b++)
#pragma unroll
            for (int c = 0; c < 4; c++) acc[a][b][c] = 0.f;

    auto lda = [&](const float* base, int k) {
        int head = k >> 5, dh = k & 31;
        return *(const float4*)(base + (size_t)head * NTOK * DH + dh);
    };

    float4 pa0 = lda(abase0, kq);
    float4 pa1 = lda(abase1, kq);
    float4 pb0 = *(const float4*)(bp0 + kq);
    float4 pb1 = *(const float4*)(bp1 + kq);

    for (int k0 = 0; k0 < 256; k0 += 16) {
        __syncthreads();
        *(uint4*)&As[lrow][kq] = make_uint4(
            cvt_tf32(pa0.x), cvt_tf32(pa0.y), cvt_tf32(pa0.z), cvt_tf32(pa0.w));
        *(uint4*)&As[lrow + 64][kq] = make_uint4(
            cvt_tf32(pa1.x), cvt_tf32(pa1.y), cvt_tf32(pa1.z), cvt_tf32(pa1.w));
        Bs[kq + 0][lrow] = cvt_tf32(pb0.x);
        Bs[kq + 1][lrow] = cvt_tf32(pb0.y);
        Bs[kq + 2][lrow] = cvt_tf32(pb0.z);
        Bs[kq + 3][lrow] = cvt_tf32(pb0.w);
        Bs[kq + 0][lrow + 64] = cvt_tf32(pb1.x);
        Bs[kq + 1][lrow + 64] = cvt_tf32(pb1.y);
        Bs[kq + 2][lrow + 64] = cvt_tf32(pb1.z);
        Bs[kq + 3][lrow + 64] = cvt_tf32(pb1.w);
        __syncthreads();
        if (k0 + 16 < 256) {
            pa0 = lda(abase0, k0 + 16 + kq);
            pa1 = lda(abase1, k0 + 16 + kq);
            pb0 = *(const float4*)(bp0 + k0 + 16 + kq);
            pb1 = *(const float4*)(bp1 + k0 + 16 + kq);
        }
#pragma unroll
        for (int k8 = 0; k8 < 16; k8 += 8) {
            unsigned af[4][4], bf[4][2];
#pragma unroll
            for (int mt = 0; mt < 4; mt++) {
                int rb = m0w + mt * 16 + g;
                af[mt][0] = As[rb][k8 + lt];
                af[mt][1] = As[rb + 8][k8 + lt];
                af[mt][2] = As[rb][k8 + lt + 4];
                af[mt][3] = As[rb + 8][k8 + lt + 4];
            }
#pragma unroll
            for (int nt = 0; nt < 4; nt++) {
                int cb = n0w + nt * 8 + g;
                bf[nt][0] = Bs[k8 + lt][cb];
                bf[nt][1] = Bs[k8 + lt + 4][cb];
            }
#pragma unroll
            for (int mt = 0; mt < 4; mt++)
#pragma unroll
                for (int nt = 0; nt < 4; nt++)
                    MMA8(acc[mt][nt], af[mt], bf[nt]);
        }
    }

#pragma unroll
    for (int mt = 0; mt < 4; mt++) {
#pragma unroll
        for (int half = 0; half < 2; half++) {
            int m = bm * 128 + m0w + mt * 16 + g + half * 8;
            int Bw = m / 294, tt = m % 294, l = tt / 49, r = tt % 49;
            float* op = out + ((size_t)((l * 256 + Bw) * 49 + r)) * 256;
#pragma unroll
            for (int nt = 0; nt < 4; nt++) {
                int n = bn * 128 + n0w + nt * 8 + 2 * lt;
                float2 v = make_float2(acc[mt][nt][half * 2],
                                       acc[mt][nt][half * 2 + 1]);
                *(float2*)(op + n) = v;
            }
        }
    }
}

// ======================================================================
extern "C" void kernel_launch(void* const* d_in, const int* in_sizes, int n_in,
                              void* d_out, int out_size) {
    const float* x          = (const float*)d_in[0];
    const float* w_qkv      = (const float*)d_in[1];
    const float* w_out      = (const float*)d_in[2];
    const float* bias_table = (const float*)d_in[3];
    float* out = (float*)d_out;

    bias_kernel<<<NTOK, NTOK>>>(bias_table);
    qkv_gemm<<<dim3(588, 6), 256>>>(x, w_qkv);

    int smem = (JT * KSTR2 + DH * VTSTR2 + 16 * SSTR + 512) * (int)sizeof(unsigned);
    cudaFuncSetAttribute(attn_kernel, cudaFuncAttributeMaxDynamicSharedMemorySize, smem);
    attn_kernel<<<NWIN * NHEAD, 256, smem>>>();

    out_gemm<<<dim3(588, 2), 256>>>(w_out, out);
}

// round 12
// speedup vs baseline: 2.9292x; 1.6209x over previous
#include <cuda_runtime.h>
#include <cuda_bf16.h>
#include <math.h>

#define NTOK 294      // 6*7*7 tokens per window
#define NWIN 256      // 16*16 windows
#define NHEAD 8
#define DH 32
#define DIM 256
#define QSCALE 0.17677669529663687f  // 32^-0.5

#define JT 320        // j padded to 40 n-tiles of 8 (5 chunks of 64)
#define BSTR 320      // bias row stride (cols 294..319 = -1e30)
#define KSTR3 36      // K smem stride: 36%32=4 -> (4g+lt) distinct banks
#define VTSTR3 324    // Vt stride: 324%32=4 -> conflict-free B frags

// -------- scratch (device globals; no allocations allowed) --------
__device__ float g_Q[(size_t)NWIN*NHEAD*NTOK*DH];
__device__ float g_K[(size_t)NWIN*NHEAD*NTOK*DH];
__device__ float g_V[(size_t)NWIN*NHEAD*NTOK*DH];
__device__ float g_O[(size_t)NWIN*NHEAD*NTOK*DH];
__device__ float g_bias[(size_t)NHEAD*NTOK*BSTR];

// ---- tf32 helpers ----
__device__ __forceinline__ unsigned cvt_tf32(float f) {
    unsigned u; asm("cvt.rna.tf32.f32 %0, %1;" : "=r"(u) : "f"(f)); return u;
}
#define MMA8(D, A, B)                                                         \
    asm volatile(                                                             \
        "mma.sync.aligned.m16n8k8.row.col.f32.tf32.tf32.f32 "                 \
        "{%0,%1,%2,%3}, {%4,%5,%6,%7}, {%8,%9}, {%0,%1,%2,%3};"               \
        : "+f"((D)[0]), "+f"((D)[1]), "+f"((D)[2]), "+f"((D)[3])              \
        : "r"((A)[0]), "r"((A)[1]), "r"((A)[2]), "r"((A)[3]),                 \
          "r"((B)[0]), "r"((B)[1]))

// ======================================================================
// 1) Bias matrix bias[h][i][jpad] with -1e30 padding cols
// ======================================================================
__global__ void bias_kernel(const float* __restrict__ table) {
    int i = blockIdx.x;
    int j = threadIdx.x;          // 0..319
    if (j >= NTOK) {
#pragma unroll
        for (int h = 0; h < NHEAD; h++)
            g_bias[((size_t)h * NTOK + i) * BSTR + j] = -1e30f;
        return;
    }
    int ai = i / 49, ri = i % 49, yi = ri / 7, xi = ri % 7;
    int aj = j / 49, rj = j % 49, yj = rj / 7, xj = rj % 7;
    int idx = (ai - aj + 5) * 169 + (yi - yj + 6) * 13 + (xi - xj + 6);
#pragma unroll
    for (int h = 0; h < NHEAD; h++)
        g_bias[((size_t)h * NTOK + i) * BSTR + j] = table[idx * NHEAD + h];
}

// ======================================================================
// 2) QKV projection: tf32 mma.sync, 128x128 tile, 8 warps (2m x 4n).
// ======================================================================
#define APAD 20
#define BPAD 136
__global__ __launch_bounds__(256, 2) void qkv_gemm(
    const float* __restrict__ x, const float* __restrict__ w) {
    __shared__ unsigned As[128][APAD];
    __shared__ unsigned Bs[16][BPAD];
    int tid = threadIdx.x;
    int bm = blockIdx.x, bn = blockIdx.y;
    int lrow = tid >> 2;
    int kq   = (tid & 3) << 2;

    const float *ap0, *ap1;
    {
        int m0 = bm * 128 + lrow;
        int Bw = m0 / 294, t = m0 % 294, l = t / 49, r = t % 49;
        ap0 = x + ((size_t)((l * 256 + Bw) * 49 + r)) * 256;
        int m1 = m0 + 64;
        Bw = m1 / 294; t = m1 % 294; l = t / 49; r = t % 49;
        ap1 = x + ((size_t)((l * 256 + Bw) * 49 + r)) * 256;
    }
    const float* bp0 = w + (size_t)(bn * 128 + lrow) * 256;
    const float* bp1 = bp0 + (size_t)64 * 256;

    int wid = tid >> 5, lane = tid & 31;
    int g = lane >> 2, lt = lane & 3;
    int m0w = (wid & 1) * 64, n0w = (wid >> 1) * 32;

    float acc[4][4][4];
#pragma unroll
    for (int a = 0; a < 4; a++)
#pragma unroll
        for (int b = 0; b < 4; b++)
#pragma unroll
            for (int c = 0; c < 4; c++) acc[a][b][c] = 0.f;

    float4 pa0 = *(const float4*)(ap0 + kq);
    float4 pa1 = *(const float4*)(ap1 + kq);
    float4 pb0 = *(const float4*)(bp0 + kq);
    float4 pb1 = *(const float4*)(bp1 + kq);

    for (int k0 = 0; k0 < 256; k0 += 16) {
        __syncthreads();
        *(uint4*)&As[lrow][kq] = make_uint4(
            cvt_tf32(pa0.x), cvt_tf32(pa0.y), cvt_tf32(pa0.z), cvt_tf32(pa0.w));
        *(uint4*)&As[lrow + 64][kq] = make_uint4(
            cvt_tf32(pa1.x), cvt_tf32(pa1.y), cvt_tf32(pa1.z), cvt_tf32(pa1.w));
        Bs[kq + 0][lrow] = cvt_tf32(pb0.x);
        Bs[kq + 1][lrow] = cvt_tf32(pb0.y);
        Bs[kq + 2][lrow] = cvt_tf32(pb0.z);
        Bs[kq + 3][lrow] = cvt_tf32(pb0.w);
        Bs[kq + 0][lrow + 64] = cvt_tf32(pb1.x);
        Bs[kq + 1][lrow + 64] = cvt_tf32(pb1.y);
        Bs[kq + 2][lrow + 64] = cvt_tf32(pb1.z);
        Bs[kq + 3][lrow + 64] = cvt_tf32(pb1.w);
        __syncthreads();
        if (k0 + 16 < 256) {
            pa0 = *(const float4*)(ap0 + k0 + 16 + kq);
            pa1 = *(const float4*)(ap1 + k0 + 16 + kq);
            pb0 = *(const float4*)(bp0 + k0 + 16 + kq);
            pb1 = *(const float4*)(bp1 + k0 + 16 + kq);
        }
#pragma unroll
        for (int k8 = 0; k8 < 16; k8 += 8) {
            unsigned af[4][4], bf[4][2];
#pragma unroll
            for (int mt = 0; mt < 4; mt++) {
                int rb = m0w + mt * 16 + g;
                af[mt][0] = As[rb][k8 + lt];
                af[mt][1] = As[rb + 8][k8 + lt];
                af[mt][2] = As[rb][k8 + lt + 4];
                af[mt][3] = As[rb + 8][k8 + lt + 4];
            }
#pragma unroll
            for (int nt = 0; nt < 4; nt++) {
                int cb = n0w + nt * 8 + g;
                bf[nt][0] = Bs[k8 + lt][cb];
                bf[nt][1] = Bs[k8 + lt + 4][cb];
            }
#pragma unroll
            for (int mt = 0; mt < 4; mt++)
#pragma unroll
                for (int nt = 0; nt < 4; nt++)
                    MMA8(acc[mt][nt], af[mt], bf[nt]);
        }
    }

#pragma unroll
    for (int mt = 0; mt < 4; mt++) {
#pragma unroll
        for (int half = 0; half < 2; half++) {
            int m = bm * 128 + m0w + mt * 16 + g + half * 8;
            int Bw = m / 294, tt = m % 294;
            size_t mb = (size_t)Bw * 8 * NTOK + tt;
#pragma unroll
            for (int nt = 0; nt < 4; nt++) {
#pragma unroll
                for (int e = 0; e < 2; e++) {
                    int n = bn * 128 + n0w + nt * 8 + 2 * lt + e;
                    int part = n >> 8, rem = n & 255;
                    int head = rem >> 5, dh = rem & 31;
                    size_t o = (mb + (size_t)head * NTOK) * DH + dh;
                    float v = acc[mt][nt][half * 2 + e];
                    if (part == 0)      g_Q[o] = v * QSCALE;
                    else if (part == 1) g_K[o] = v;
                    else                g_V[o] = v;
                }
            }
        }
    }
}

// ======================================================================
// 3) Attention: warp-independent flash. Each warp owns 16-row m-tiles
//    (tiles w, w+8, w+16); online softmax in registers; QK D-frag ->
//    AV A-frag via intra-quad shuffles. No mainloop barriers.
// ======================================================================
__global__ __launch_bounds__(256, 2) void attn_kernel() {
    int bh = blockIdx.x;            // Bw*8 + h
    int h = bh & 7;
    extern __shared__ unsigned smu[];
    unsigned* Ks = smu;                    // 320*36  = 11520
    unsigned* Vt = Ks + JT * KSTR3;        // 32*324  = 10368
    // total 21888 words = 87.6 KB -> 2 blocks/SM

    const float* Kg = g_K + (size_t)bh * NTOK * DH;
    const float* Vg = g_V + (size_t)bh * NTOK * DH;
    const float* Qg = g_Q + (size_t)bh * NTOK * DH;
    const float* Bbp = g_bias + (size_t)h * NTOK * BSTR;

    int tid = threadIdx.x;
    for (int idx = tid; idx < JT * DH; idx += 256) {
        int j = idx >> 5, d = idx & 31;
        float kv = (j < NTOK) ? Kg[j * DH + d] : 0.f;
        float vv = (j < NTOK) ? Vg[j * DH + d] : 0.f;
        Ks[j * KSTR3 + d] = cvt_tf32(kv);
        Vt[d * VTSTR3 + j] = cvt_tf32(vv);
    }
    __syncthreads();

    int w = tid >> 5, lane = tid & 31;
    int g = lane >> 2, lt = lane & 3;
    int qbase = lane & ~3;              // first lane of this quad
    int srcA = qbase + (lt >> 1);       // perm source for cols lt
    int srcB = qbase + 2 + (lt >> 1);   // perm source for cols lt+4
    bool odd = (lt & 1);

    for (int tile = w; tile < 19; tile += 8) {
        int i0 = tile * 16;
        int r0 = i0 + g;     if (r0 >= NTOK) r0 = NTOK - 1;
        int r1 = i0 + g + 8; if (r1 >= NTOK) r1 = NTOK - 1;

        // Q A-fragments (this warp only)
        unsigned qf[4][4];
#pragma unroll
        for (int k8 = 0; k8 < 4; k8++) {
            qf[k8][0] = cvt_tf32(Qg[r0 * DH + k8 * 8 + lt]);
            qf[k8][1] = cvt_tf32(Qg[r1 * DH + k8 * 8 + lt]);
            qf[k8][2] = cvt_tf32(Qg[r0 * DH + k8 * 8 + lt + 4]);
            qf[k8][3] = cvt_tf32(Qg[r1 * DH + k8 * 8 + lt + 4]);
        }
        const float* br0 = Bbp + (size_t)r0 * BSTR;
        const float* br1 = Bbp + (size_t)r1 * BSTR;

        float m0 = -1e30f, m1 = -1e30f, l0 = 0.f, l1 = 0.f;
        float O[4][4];
#pragma unroll
        for (int dt = 0; dt < 4; dt++)
#pragma unroll
            for (int e = 0; e < 4; e++) O[dt][e] = 0.f;

        for (int c = 0; c < 5; c++) {
            // ---- QK for 8 n-tiles (64 cols), bias fused ----
            float s[8][4];
#pragma unroll
            for (int n = 0; n < 8; n++) {
                int nt = c * 8 + n;
                float acc[4] = {0.f, 0.f, 0.f, 0.f};
                const unsigned* kb = Ks + (nt * 8 + g) * KSTR3;
#pragma unroll
                for (int k8 = 0; k8 < 4; k8++) {
                    unsigned bf[2] = { kb[k8 * 8 + lt], kb[k8 * 8 + lt + 4] };
                    MMA8(acc, qf[k8], bf);
                }
                float2 b0v = *(const float2*)(br0 + nt * 8 + 2 * lt);
                float2 b1v = *(const float2*)(br1 + nt * 8 + 2 * lt);
                s[n][0] = acc[0] + b0v.x; s[n][1] = acc[1] + b0v.y;
                s[n][2] = acc[2] + b1v.x; s[n][3] = acc[3] + b1v.y;
            }

            // ---- online softmax update ----
            float cm0 = -1e30f, cm1 = -1e30f;
#pragma unroll
            for (int n = 0; n < 8; n++) {
                cm0 = fmaxf(cm0, fmaxf(s[n][0], s[n][1]));
                cm1 = fmaxf(cm1, fmaxf(s[n][2], s[n][3]));
            }
            cm0 = fmaxf(cm0, __shfl_xor_sync(0xffffffffu, cm0, 1));
            cm0 = fmaxf(cm0, __shfl_xor_sync(0xffffffffu, cm0, 2));
            cm1 = fmaxf(cm1, __shfl_xor_sync(0xffffffffu, cm1, 1));
            cm1 = fmaxf(cm1, __shfl_xor_sync(0xffffffffu, cm1, 2));
            float nm0 = fmaxf(m0, cm0), nm1 = fmaxf(m1, cm1);
            float f0 = __expf(m0 - nm0), f1 = __expf(m1 - nm1);
            m0 = nm0; m1 = nm1;

            float sum0 = 0.f, sum1 = 0.f;
#pragma unroll
            for (int n = 0; n < 8; n++) {
                s[n][0] = __expf(s[n][0] - m0); sum0 += s[n][0];
                s[n][1] = __expf(s[n][1] - m0); sum0 += s[n][1];
                s[n][2] = __expf(s[n][2] - m1); sum1 += s[n][2];
                s[n][3] = __expf(s[n][3] - m1); sum1 += s[n][3];
            }
            sum0 += __shfl_xor_sync(0xffffffffu, sum0, 1);
            sum0 += __shfl_xor_sync(0xffffffffu, sum0, 2);
            sum1 += __shfl_xor_sync(0xffffffffu, sum1, 1);
            sum1 += __shfl_xor_sync(0xffffffffu, sum1, 2);
            l0 = l0 * f0 + sum0;
            l1 = l1 * f1 + sum1;

#pragma unroll
            for (int dt = 0; dt < 4; dt++) {
                O[dt][0] *= f0; O[dt][1] *= f0;
                O[dt][2] *= f1; O[dt][3] *= f1;
            }

            // ---- permute D->A frags and AV-accumulate ----
#pragma unroll
            for (int n = 0; n < 8; n++) {
                int j0 = (c * 8 + n) * 8;
                float t0 = __shfl_sync(0xffffffffu, s[n][0], srcA);
                float t1 = __shfl_sync(0xffffffffu, s[n][1], srcA);
                float t2 = __shfl_sync(0xffffffffu, s[n][0], srcB);
                float t3 = __shfl_sync(0xffffffffu, s[n][1], srcB);
                float u0 = __shfl_sync(0xffffffffu, s[n][2], srcA);
                float u1 = __shfl_sync(0xffffffffu, s[n][3], srcA);
                float u2 = __shfl_sync(0xffffffffu, s[n][2], srcB);
                float u3 = __shfl_sync(0xffffffffu, s[n][3], srcB);
                unsigned af[4];
                af[0] = cvt_tf32(odd ? t1 : t0);   // P(g,   lt)
                af[1] = cvt_tf32(odd ? u1 : u0);   // P(g+8, lt)
                af[2] = cvt_tf32(odd ? t3 : t2);   // P(g,   lt+4)
                af[3] = cvt_tf32(odd ? u3 : u2);   // P(g+8, lt+4)
#pragma unroll
                for (int dt = 0; dt < 4; dt++) {
                    const unsigned* vb = Vt + (dt * 8 + g) * VTSTR3;
                    unsigned bf[2] = { vb[j0 + lt], vb[j0 + lt + 4] };
                    MMA8(O[dt], af, bf);
                }
            }
        }

        // ---- finalize + store ----
        float inv0 = 1.f / l0, inv1 = 1.f / l1;
        int ia = i0 + g, ib = i0 + g + 8;
        float* ob = g_O + (size_t)bh * NTOK * DH;
#pragma unroll
        for (int dt = 0; dt < 4; dt++) {
            if (ia < NTOK)
                *(float2*)(ob + ia * DH + dt * 8 + 2 * lt) =
                    make_float2(O[dt][0] * inv0, O[dt][1] * inv0);
            if (ib < NTOK)
                *(float2*)(ob + ib * DH + dt * 8 + 2 * lt) =
                    make_float2(O[dt][2] * inv1, O[dt][3] * inv1);
        }
    }
}

// ======================================================================
// 4) Output projection: tf32 mma.sync, fused gather from g_O + scatter.
// ======================================================================
__global__ __launch_bounds__(256, 2) void out_gemm(
    const float* __restrict__ w, float* __restrict__ out) {
    __shared__ unsigned As[128][APAD];
    __shared__ unsigned Bs[16][BPAD];
    int tid = threadIdx.x;
    int bm = blockIdx.x, bn = blockIdx.y;
    int lrow = tid >> 2;
    int kq   = (tid & 3) << 2;

    int m0 = bm * 128 + lrow;
    int Bw0 = m0 / 294, t0 = m0 % 294;
    int m1 = m0 + 64;
    int Bw1 = m1 / 294, t1 = m1 % 294;
    const float* abase0 = g_O + ((size_t)Bw0 * 8 * NTOK + t0) * DH;
    const float* abase1 = g_O + ((size_t)Bw1 * 8 * NTOK + t1) * DH;

    const float* bp0 = w + (size_t)(bn * 128 + lrow) * 256;
    const float* bp1 = bp0 + (size_t)64 * 256;

    int wid = tid >> 5, lane = tid & 31;
    int g = lane >> 2, lt = lane & 3;
    int m0w = (wid & 1) * 64, n0w = (wid >> 1) * 32;

    float acc[4][4][4];
#pragma unroll
    for (int a = 0; a < 4; a++)
#pragma unroll
        for (int b = 0; b < 4; b++)
#pragma unroll
            for (int c = 0; c < 4; c++) acc[a][b][c] = 0.f;

    auto lda = [&](const float* base, int k) {
        int head = k >> 5, dh = k & 31;
        return *(const float4*)(base + (size_t)head * NTOK * DH + dh);
    };

    float4 pa0 = lda(abase0, kq);
    float4 pa1 = lda(abase1, kq);
    float4 pb0 = *(const float4*)(bp0 + kq);
    float4 pb1 = *(const float4*)(bp1 + kq);

    for (int k0 = 0; k0 < 256; k0 += 16) {
        __syncthreads();
        *(uint4*)&As[lrow][kq] = make_uint4(
            cvt_tf32(pa0.x), cvt_tf32(pa0.y), cvt_tf32(pa0.z), cvt_tf32(pa0.w));
        *(uint4*)&As[lrow + 64][kq] = make_uint4(
            cvt_tf32(pa1.x), cvt_tf32(pa1.y), cvt_tf32(pa1.z), cvt_tf32(pa1.w));
        Bs[kq + 0][lrow] = cvt_tf32(pb0.x);
        Bs[kq + 1][lrow] = cvt_tf32(pb0.y);
        Bs[kq + 2][lrow] = cvt_tf32(pb0.z);
        Bs[kq + 3][lrow] = cvt_tf32(pb0.w);
        Bs[kq + 0][lrow + 64] = cvt_tf32(pb1.x);
        Bs[kq + 1][lrow + 64] = cvt_tf32(pb1.y);
        Bs[kq + 2][lrow + 64] = cvt_tf32(pb1.z);
        Bs[kq + 3][lrow + 64] = cvt_tf32(pb1.w);
        __syncthreads();
        if (k0 + 16 < 256) {
            pa0 = lda(abase0, k0 + 16 + kq);
            pa1 = lda(abase1, k0 + 16 + kq);
            pb0 = *(const float4*)(bp0 + k0 + 16 + kq);
            pb1 = *(const float4*)(bp1 + k0 + 16 + kq);
        }
#pragma unroll
        for (int k8 = 0; k8 < 16; k8 += 8) {
            unsigned af[4][4], bf[4][2];
#pragma unroll
            for (int mt = 0; mt < 4; mt++) {
                int rb = m0w + mt * 16 + g;
                af[mt][0] = As[rb][k8 + lt];
                af[mt][1] = As[rb + 8][k8 + lt];
                af[mt][2] = As[rb][k8 + lt + 4];
                af[mt][3] = As[rb + 8][k8 + lt + 4];
            }
#pragma unroll
            for (int nt = 0; nt < 4; nt++) {
                int cb = n0w + nt * 8 + g;
                bf[nt][0] = Bs[k8 + lt][cb];
                bf[nt][1] = Bs[k8 + lt + 4][cb];
            }
#pragma unroll
            for (int mt = 0; mt < 4; mt++)
#pragma unroll
                for (int nt = 0; nt < 4; nt++)
                    MMA8(acc[mt][nt], af[mt], bf[nt]);
        }
    }

#pragma unroll
    for (int mt = 0; mt < 4; mt++) {
#pragma unroll
        for (int half = 0; half < 2; half++) {
            int m = bm * 128 + m0w + mt * 16 + g + half * 8;
            int Bw = m / 294, tt = m % 294, l = tt / 49, r = tt % 49;
            float* op = out + ((size_t)((l * 256 + Bw) * 49 + r)) * 256;
#pragma unroll
            for (int nt = 0; nt < 4; nt++) {
                int n = bn * 128 + n0w + nt * 8 + 2 * lt;
                float2 v = make_float2(acc[mt][nt][half * 2],
                                       acc[mt][nt][half * 2 + 1]);
                *(float2*)(op + n) = v;
            }
        }
    }
}

// ======================================================================
extern "C" void kernel_launch(void* const* d_in, const int* in_sizes, int n_in,
                              void* d_out, int out_size) {
    const float* x          = (const float*)d_in[0];
    const float* w_qkv      = (const float*)d_in[1];
    const float* w_out      = (const float*)d_in[2];
    const float* bias_table = (const float*)d_in[3];
    float* out = (float*)d_out;

    bias_kernel<<<NTOK, BSTR>>>(bias_table);
    qkv_gemm<<<dim3(588, 6), 256>>>(x, w_qkv);

    int smem = (JT * KSTR3 + DH * VTSTR3) * (int)sizeof(unsigned);
    cudaFuncSetAttribute(attn_kernel, cudaFuncAttributeMaxDynamicSharedMemorySize, smem);
    attn_kernel<<<NWIN * NHEAD, 256, smem>>>();

    out_gemm<<<dim3(588, 2), 256>>>(w_out, out);
}

// round 13
// speedup vs baseline: 3.1806x; 1.0858x over previous
#include <cuda_runtime.h>
#include <cuda_bf16.h>
#include <math.h>

#define NTOK 294      // 6*7*7 tokens per window
#define NWIN 256      // 16*16 windows
#define NHEAD 8
#define DH 32
#define DIM 256
#define QSCALE 0.17677669529663687f  // 32^-0.5

#define JT 320        // j padded to 40 n-tiles of 8 (5 chunks of 64)
#define BSTR 320      // bias row stride (cols 294..319 = -1e30)
#define KSTR3 36      // K smem stride: 36%32=4 -> conflict-free B frags
#define VTSTR3 324    // Vt stride: 324%32=4 -> conflict-free B frags

// -------- scratch (device globals; no allocations allowed) --------
__device__ float g_Q[(size_t)NWIN*NHEAD*NTOK*DH];
__device__ float g_K[(size_t)NWIN*NHEAD*NTOK*DH];
__device__ float g_V[(size_t)NWIN*NHEAD*NTOK*DH];
__device__ float g_O[(size_t)NWIN*NHEAD*NTOK*DH];
__device__ float g_bias[(size_t)NHEAD*NTOK*BSTR];

// ---- tf32 / async helpers ----
__device__ __forceinline__ unsigned cvt_tf32(float f) {
    unsigned u; asm("cvt.rna.tf32.f32 %0, %1;" : "=r"(u) : "f"(f)); return u;
}
#define MMA8(D, A, B)                                                         \
    asm volatile(                                                             \
        "mma.sync.aligned.m16n8k8.row.col.f32.tf32.tf32.f32 "                 \
        "{%0,%1,%2,%3}, {%4,%5,%6,%7}, {%8,%9}, {%0,%1,%2,%3};"               \
        : "+f"((D)[0]), "+f"((D)[1]), "+f"((D)[2]), "+f"((D)[3])              \
        : "r"((A)[0]), "r"((A)[1]), "r"((A)[2]), "r"((A)[3]),                 \
          "r"((B)[0]), "r"((B)[1]))

__device__ __forceinline__ void cp_async16(float* s, const float* g) {
    unsigned sa = (unsigned)__cvta_generic_to_shared(s);
    asm volatile("cp.async.cg.shared.global [%0], [%1], 16;" :: "r"(sa), "l"(g));
}
#define CP_COMMIT() asm volatile("cp.async.commit_group;")
#define CP_WAIT2()  asm volatile("cp.async.wait_group 2;")

#define STAGES 4
#define TSTR 20     // per-stage row stride in floats (16 data + 4 pad)
#define STAGE_WORDS (256 * TSTR)      // A[128][20] + B[128][20]
#define GEMM_SMEM (STAGES * STAGE_WORDS * 4)   // 81920 bytes

// ======================================================================
// 1) Bias matrix bias[h][i][jpad] with -1e30 padding cols
// ======================================================================
__global__ void bias_kernel(const float* __restrict__ table) {
    int i = blockIdx.x;
    int j = threadIdx.x;          // 0..319
    if (j >= NTOK) {
#pragma unroll
        for (int h = 0; h < NHEAD; h++)
            g_bias[((size_t)h * NTOK + i) * BSTR + j] = -1e30f;
        return;
    }
    int ai = i / 49, ri = i % 49, yi = ri / 7, xi = ri % 7;
    int aj = j / 49, rj = j % 49, yj = rj / 7, xj = rj % 7;
    int idx = (ai - aj + 5) * 169 + (yi - yj + 6) * 13 + (xi - xj + 6);
#pragma unroll
    for (int h = 0; h < NHEAD; h++)
        g_bias[((size_t)h * NTOK + i) * BSTR + j] = table[idx * NHEAD + h];
}

// ======================================================================
// 2) QKV projection: tf32 mma.sync, 4-stage cp.async pipeline.
// ======================================================================
__global__ __launch_bounds__(256, 2) void qkv_gemm(
    const float* __restrict__ x, const float* __restrict__ w) {
    extern __shared__ float smf[];
    int tid = threadIdx.x;
    int bm = blockIdx.x, bn = blockIdx.y;
    int row = tid >> 2;           // 0..63
    int chunk = tid & 3;          // 4-float chunk within 16

    // A row gather pointers (two rows per thread)
    const float *ap0, *ap1;
    {
        int m0 = bm * 128 + row;
        int Bw = m0 / 294, t = m0 % 294, l = t / 49, r = t % 49;
        ap0 = x + ((size_t)((l * 256 + Bw) * 49 + r)) * 256;
        int m1 = m0 + 64;
        Bw = m1 / 294; t = m1 % 294; l = t / 49; r = t % 49;
        ap1 = x + ((size_t)((l * 256 + Bw) * 49 + r)) * 256;
    }
    const float* bp0 = w + (size_t)(bn * 128 + row) * 256;
    const float* bp1 = bp0 + (size_t)64 * 256;

    int wid = tid >> 5, lane = tid & 31;
    int g = lane >> 2, lt = lane & 3;
    int m0w = (wid & 1) * 64, n0w = (wid >> 1) * 32;

    float acc[4][4][4];
#pragma unroll
    for (int a = 0; a < 4; a++)
#pragma unroll
        for (int b = 0; b < 4; b++)
#pragma unroll
            for (int c = 0; c < 4; c++) acc[a][b][c] = 0.f;

    auto load_tile = [&](int s, int kt) {
        float* A = smf + s * STAGE_WORDS;
        float* B = A + 128 * TSTR;
        int k0 = kt * 16 + chunk * 4;
        cp_async16(A + row * TSTR + chunk * 4, ap0 + k0);
        cp_async16(A + (row + 64) * TSTR + chunk * 4, ap1 + k0);
        cp_async16(B + row * TSTR + chunk * 4, bp0 + k0);
        cp_async16(B + (row + 64) * TSTR + chunk * 4, bp1 + k0);
    };

#pragma unroll
    for (int s = 0; s < STAGES - 1; s++) { load_tile(s, s); CP_COMMIT(); }

    for (int t = 0; t < 16; t++) {
        CP_WAIT2();
        __syncthreads();
        int ld = t + STAGES - 1;
        if (ld < 16) load_tile(ld & 3, ld);
        CP_COMMIT();

        const float* A = smf + (t & 3) * STAGE_WORDS;
        const float* B = A + 128 * TSTR;
#pragma unroll
        for (int k8 = 0; k8 < 16; k8 += 8) {
            unsigned af[4][4], bf[4][2];
#pragma unroll
            for (int mt = 0; mt < 4; mt++) {
                int rb = m0w + mt * 16 + g;
                af[mt][0] = cvt_tf32(A[rb * TSTR + k8 + lt]);
                af[mt][1] = cvt_tf32(A[(rb + 8) * TSTR + k8 + lt]);
                af[mt][2] = cvt_tf32(A[rb * TSTR + k8 + lt + 4]);
                af[mt][3] = cvt_tf32(A[(rb + 8) * TSTR + k8 + lt + 4]);
            }
#pragma unroll
            for (int nt = 0; nt < 4; nt++) {
                int cb = n0w + nt * 8 + g;
                bf[nt][0] = cvt_tf32(B[cb * TSTR + k8 + lt]);
                bf[nt][1] = cvt_tf32(B[cb * TSTR + k8 + lt + 4]);
            }
#pragma unroll
            for (int mt = 0; mt < 4; mt++)
#pragma unroll
                for (int nt = 0; nt < 4; nt++)
                    MMA8(acc[mt][nt], af[mt], bf[nt]);
        }
    }

    // epilogue: scatter into Q/K/V
#pragma unroll
    for (int mt = 0; mt < 4; mt++) {
#pragma unroll
        for (int half = 0; half < 2; half++) {
            int m = bm * 128 + m0w + mt * 16 + g + half * 8;
            int Bw = m / 294, tt = m % 294;
            size_t mb = (size_t)Bw * 8 * NTOK + tt;
#pragma unroll
            for (int nt = 0; nt < 4; nt++) {
#pragma unroll
                for (int e = 0; e < 2; e++) {
                    int n = bn * 128 + n0w + nt * 8 + 2 * lt + e;
                    int part = n >> 8, rem = n & 255;
                    int head = rem >> 5, dh = rem & 31;
                    size_t o = (mb + (size_t)head * NTOK) * DH + dh;
                    float v = acc[mt][nt][half * 2 + e];
                    if (part == 0)      g_Q[o] = v * QSCALE;
                    else if (part == 1) g_K[o] = v;
                    else                g_V[o] = v;
                }
            }
        }
    }
}

// ======================================================================
// 3) Attention: warp-independent flash (unchanged from R12).
// ======================================================================
__global__ __launch_bounds__(256, 2) void attn_kernel() {
    int bh = blockIdx.x;            // Bw*8 + h
    int h = bh & 7;
    extern __shared__ unsigned smu[];
    unsigned* Ks = smu;                    // 320*36
    unsigned* Vt = Ks + JT * KSTR3;        // 32*324

    const float* Kg = g_K + (size_t)bh * NTOK * DH;
    const float* Vg = g_V + (size_t)bh * NTOK * DH;
    const float* Qg = g_Q + (size_t)bh * NTOK * DH;
    const float* Bbp = g_bias + (size_t)h * NTOK * BSTR;

    int tid = threadIdx.x;
    for (int idx = tid; idx < JT * DH; idx += 256) {
        int j = idx >> 5, d = idx & 31;
        float kv = (j < NTOK) ? Kg[j * DH + d] : 0.f;
        float vv = (j < NTOK) ? Vg[j * DH + d] : 0.f;
        Ks[j * KSTR3 + d] = cvt_tf32(kv);
        Vt[d * VTSTR3 + j] = cvt_tf32(vv);
    }
    __syncthreads();

    int w = tid >> 5, lane = tid & 31;
    int g = lane >> 2, lt = lane & 3;
    int qbase = lane & ~3;
    int srcA = qbase + (lt >> 1);
    int srcB = qbase + 2 + (lt >> 1);
    bool odd = (lt & 1);

    for (int tile = w; tile < 19; tile += 8) {
        int i0 = tile * 16;
        int r0 = i0 + g;     if (r0 >= NTOK) r0 = NTOK - 1;
        int r1 = i0 + g + 8; if (r1 >= NTOK) r1 = NTOK - 1;

        unsigned qf[4][4];
#pragma unroll
        for (int k8 = 0; k8 < 4; k8++) {
            qf[k8][0] = cvt_tf32(Qg[r0 * DH + k8 * 8 + lt]);
            qf[k8][1] = cvt_tf32(Qg[r1 * DH + k8 * 8 + lt]);
            qf[k8][2] = cvt_tf32(Qg[r0 * DH + k8 * 8 + lt + 4]);
            qf[k8][3] = cvt_tf32(Qg[r1 * DH + k8 * 8 + lt + 4]);
        }
        const float* br0 = Bbp + (size_t)r0 * BSTR;
        const float* br1 = Bbp + (size_t)r1 * BSTR;

        float m0 = -1e30f, m1 = -1e30f, l0 = 0.f, l1 = 0.f;
        float O[4][4];
#pragma unroll
        for (int dt = 0; dt < 4; dt++)
#pragma unroll
            for (int e = 0; e < 4; e++) O[dt][e] = 0.f;

        for (int c = 0; c < 5; c++) {
            float s[8][4];
#pragma unroll
            for (int n = 0; n < 8; n++) {
                int nt = c * 8 + n;
                float acc[4] = {0.f, 0.f, 0.f, 0.f};
                const unsigned* kb = Ks + (nt * 8 + g) * KSTR3;
#pragma unroll
                for (int k8 = 0; k8 < 4; k8++) {
                    unsigned bf[2] = { kb[k8 * 8 + lt], kb[k8 * 8 + lt + 4] };
                    MMA8(acc, qf[k8], bf);
                }
                float2 b0v = *(const float2*)(br0 + nt * 8 + 2 * lt);
                float2 b1v = *(const float2*)(br1 + nt * 8 + 2 * lt);
                s[n][0] = acc[0] + b0v.x; s[n][1] = acc[1] + b0v.y;
                s[n][2] = acc[2] + b1v.x; s[n][3] = acc[3] + b1v.y;
            }

            float cm0 = -1e30f, cm1 = -1e30f;
#pragma unroll
            for (int n = 0; n < 8; n++) {
                cm0 = fmaxf(cm0, fmaxf(s[n][0], s[n][1]));
                cm1 = fmaxf(cm1, fmaxf(s[n][2], s[n][3]));
            }
            cm0 = fmaxf(cm0, __shfl_xor_sync(0xffffffffu, cm0, 1));
            cm0 = fmaxf(cm0, __shfl_xor_sync(0xffffffffu, cm0, 2));
            cm1 = fmaxf(cm1, __shfl_xor_sync(0xffffffffu, cm1, 1));
            cm1 = fmaxf(cm1, __shfl_xor_sync(0xffffffffu, cm1, 2));
            float nm0 = fmaxf(m0, cm0), nm1 = fmaxf(m1, cm1);
            float f0 = __expf(m0 - nm0), f1 = __expf(m1 - nm1);
            m0 = nm0; m1 = nm1;

            float sum0 = 0.f, sum1 = 0.f;
#pragma unroll
            for (int n = 0; n < 8; n++) {
                s[n][0] = __expf(s[n][0] - m0); sum0 += s[n][0];
                s[n][1] = __expf(s[n][1] - m0); sum0 += s[n][1];
                s[n][2] = __expf(s[n][2] - m1); sum1 += s[n][2];
                s[n][3] = __expf(s[n][3] - m1); sum1 += s[n][3];
            }
            sum0 += __shfl_xor_sync(0xffffffffu, sum0, 1);
            sum0 += __shfl_xor_sync(0xffffffffu, sum0, 2);
            sum1 += __shfl_xor_sync(0xffffffffu, sum1, 1);
            sum1 += __shfl_xor_sync(0xffffffffu, sum1, 2);
            l0 = l0 * f0 + sum0;
            l1 = l1 * f1 + sum1;

#pragma unroll
            for (int dt = 0; dt < 4; dt++) {
                O[dt][0] *= f0; O[dt][1] *= f0;
                O[dt][2] *= f1; O[dt][3] *= f1;
            }

#pragma unroll
            for (int n = 0; n < 8; n++) {
                int j0 = (c * 8 + n) * 8;
                float t0 = __shfl_sync(0xffffffffu, s[n][0], srcA);
                float t1 = __shfl_sync(0xffffffffu, s[n][1], srcA);
                float t2 = __shfl_sync(0xffffffffu, s[n][0], srcB);
                float t3 = __shfl_sync(0xffffffffu, s[n][1], srcB);
                float u0 = __shfl_sync(0xffffffffu, s[n][2], srcA);
                float u1 = __shfl_sync(0xffffffffu, s[n][3], srcA);
                float u2 = __shfl_sync(0xffffffffu, s[n][2], srcB);
                float u3 = __shfl_sync(0xffffffffu, s[n][3], srcB);
                unsigned af[4];
                af[0] = cvt_tf32(odd ? t1 : t0);
                af[1] = cvt_tf32(odd ? u1 : u0);
                af[2] = cvt_tf32(odd ? t3 : t2);
                af[3] = cvt_tf32(odd ? u3 : u2);
#pragma unroll
                for (int dt = 0; dt < 4; dt++) {
                    const unsigned* vb = Vt + (dt * 8 + g) * VTSTR3;
                    unsigned bf[2] = { vb[j0 + lt], vb[j0 + lt + 4] };
                    MMA8(O[dt], af, bf);
                }
            }
        }

        float inv0 = 1.f / l0, inv1 = 1.f / l1;
        int ia = i0 + g, ib = i0 + g + 8;
        float* ob = g_O + (size_t)bh * NTOK * DH;
#pragma unroll
        for (int dt = 0; dt < 4; dt++) {
            if (ia < NTOK)
                *(float2*)(ob + ia * DH + dt * 8 + 2 * lt) =
                    make_float2(O[dt][0] * inv0, O[dt][1] * inv0);
            if (ib < NTOK)
                *(float2*)(ob + ib * DH + dt * 8 + 2 * lt) =
                    make_float2(O[dt][2] * inv1, O[dt][3] * inv1);
        }
    }
}

// ======================================================================
// 4) Output projection: tf32 mma.sync, 4-stage cp.async pipeline.
// ======================================================================
__global__ __launch_bounds__(256, 2) void out_gemm(
    const float* __restrict__ w, float* __restrict__ out) {
    extern __shared__ float smf[];
    int tid = threadIdx.x;
    int bm = blockIdx.x, bn = blockIdx.y;
    int row = tid >> 2;
    int chunk = tid & 3;

    int m0 = bm * 128 + row;
    int Bw0 = m0 / 294, t0 = m0 % 294;
    int m1 = m0 + 64;
    int Bw1 = m1 / 294, t1 = m1 % 294;
    const float* abase0 = g_O + ((size_t)Bw0 * 8 * NTOK + t0) * DH;
    const float* abase1 = g_O + ((size_t)Bw1 * 8 * NTOK + t1) * DH;

    const float* bp0 = w + (size_t)(bn * 128 + row) * 256;
    const float* bp1 = bp0 + (size_t)64 * 256;

    int wid = tid >> 5, lane = tid & 31;
    int g = lane >> 2, lt = lane & 3;
    int m0w = (wid & 1) * 64, n0w = (wid >> 1) * 32;

    float acc[4][4][4];
#pragma unroll
    for (int a = 0; a < 4; a++)
#pragma unroll
        for (int b = 0; b < 4; b++)
#pragma unroll
            for (int c = 0; c < 4; c++) acc[a][b][c] = 0.f;

    auto load_tile = [&](int s, int kt) {
        float* A = smf + s * STAGE_WORDS;
        float* B = A + 128 * TSTR;
        int k = kt * 16 + chunk * 4;         // 16B chunk stays in one head
        int head = k >> 5, dh = k & 31;
        size_t go = (size_t)head * NTOK * DH + dh;
        cp_async16(A + row * TSTR + chunk * 4, abase0 + go);
        cp_async16(A + (row + 64) * TSTR + chunk * 4, abase1 + go);
        cp_async16(B + row * TSTR + chunk * 4, bp0 + k);
        cp_async16(B + (row + 64) * TSTR + chunk * 4, bp1 + k);
    };

#pragma unroll
    for (int s = 0; s < STAGES - 1; s++) { load_tile(s, s); CP_COMMIT(); }

    for (int t = 0; t < 16; t++) {
        CP_WAIT2();
        __syncthreads();
        int ld = t + STAGES - 1;
        if (ld < 16) load_tile(ld & 3, ld);
        CP_COMMIT();

        const float* A = smf + (t & 3) * STAGE_WORDS;
        const float* B = A + 128 * TSTR;
#pragma unroll
        for (int k8 = 0; k8 < 16; k8 += 8) {
            unsigned af[4][4], bf[4][2];
#pragma unroll
            for (int mt = 0; mt < 4; mt++) {
                int rb = m0w + mt * 16 + g;
                af[mt][0] = cvt_tf32(A[rb * TSTR + k8 + lt]);
                af[mt][1] = cvt_tf32(A[(rb + 8) * TSTR + k8 + lt]);
                af[mt][2] = cvt_tf32(A[rb * TSTR + k8 + lt + 4]);
                af[mt][3] = cvt_tf32(A[(rb + 8) * TSTR + k8 + lt + 4]);
            }
#pragma unroll
            for (int nt = 0; nt < 4; nt++) {
                int cb = n0w + nt * 8 + g;
                bf[nt][0] = cvt_tf32(B[cb * TSTR + k8 + lt]);
                bf[nt][1] = cvt_tf32(B[cb * TSTR + k8 + lt + 4]);
            }
#pragma unroll
            for (int mt = 0; mt < 4; mt++)
#pragma unroll
                for (int nt = 0; nt < 4; nt++)
                    MMA8(acc[mt][nt], af[mt], bf[nt]);
        }
    }

#pragma unroll
    for (int mt = 0; mt < 4; mt++) {
#pragma unroll
        for (int half = 0; half < 2; half++) {
            int m = bm * 128 + m0w + mt * 16 + g + half * 8;
            int Bw = m / 294, tt = m % 294, l = tt / 49, r = tt % 49;
            float* op = out + ((size_t)((l * 256 + Bw) * 49 + r)) * 256;
#pragma unroll
            for (int nt = 0; nt < 4; nt++) {
                int n = bn * 128 + n0w + nt * 8 + 2 * lt;
                float2 v = make_float2(acc[mt][nt][half * 2],
                                       acc[mt][nt][half * 2 + 1]);
                *(float2*)(op + n) = v;
            }
        }
    }
}

// ======================================================================
extern "C" void kernel_launch(void* const* d_in, const int* in_sizes, int n_in,
                              void* d_out, int out_size) {
    const float* x          = (const float*)d_in[0];
    const float* w_qkv      = (const float*)d_in[1];
    const float* w_out      = (const float*)d_in[2];
    const float* bias_table = (const float*)d_in[3];
    float* out = (float*)d_out;

    bias_kernel<<<NTOK, BSTR>>>(bias_table);

    cudaFuncSetAttribute(qkv_gemm, cudaFuncAttributeMaxDynamicSharedMemorySize, GEMM_SMEM);
    qkv_gemm<<<dim3(588, 6), 256, GEMM_SMEM>>>(x, w_qkv);

    int smem = (JT * KSTR3 + DH * VTSTR3) * (int)sizeof(unsigned);
    cudaFuncSetAttribute(attn_kernel, cudaFuncAttributeMaxDynamicSharedMemorySize, smem);
    attn_kernel<<<NWIN * NHEAD, 256, smem>>>();

    cudaFuncSetAttribute(out_gemm, cudaFuncAttributeMaxDynamicSharedMemorySize, GEMM_SMEM);
    out_gemm<<<dim3(588, 2), 256, GEMM_SMEM>>>(w_out, out);
}